// round 12
// baseline (speedup 1.0000x reference)
#include <cuda_runtime.h>
#include <math.h>

// Problem constants
#define E   1024
#define NH  16
#define HD  64
#define SQ  2048
#define BS  2
#define TB  (SQ*BS)       // 4096
#define BH  (BS*NH)       // 32
#define OUT0 ((size_t)SQ*BS*E)

// Scratch
__device__ float g_q[BH*SQ*HD];
__device__ float g_k[BH*SQ*HD];
__device__ float g_v[BH*SQ*HD];
__device__ float g_ctx[TB*E];
__device__ float g_rowinv[BH*SQ];

// ---------------------------------------------------------------------------
// tf32 helpers
// ---------------------------------------------------------------------------
__device__ __forceinline__ unsigned f2tf(float f) {
    unsigned r;
    asm("cvt.rna.tf32.f32 %0, %1;" : "=r"(r) : "f"(f));
    return r;
}

__device__ __forceinline__ void mma8(float* c,
                                     unsigned a0, unsigned a1, unsigned a2, unsigned a3,
                                     unsigned b0, unsigned b1) {
    asm volatile(
        "mma.sync.aligned.m16n8k8.row.col.f32.tf32.tf32.f32 "
        "{%0,%1,%2,%3}, {%4,%5,%6,%7}, {%8,%9}, {%0,%1,%2,%3};\n"
        : "+f"(c[0]), "+f"(c[1]), "+f"(c[2]), "+f"(c[3])
        : "r"(a0), "r"(a1), "r"(a2), "r"(a3), "r"(b0), "r"(b1));
}

// K-interleave within each 8-wide block: k -> 2*(k&3) + ((k>>2)&1).
// Makes fragment pairs (tg, tg+4) adjacent -> LDS.64.

// ===========================================================================
// Kernel 1: QKV projection (pipelined 128x128 tf32 GEMM, paired LDS).
// Dyn smem: As[2][128][24] | Bs[2][128][24]  (both [row][k-interleaved])
// ===========================================================================
#define PR_SMEM_BYTES ((2*128*24 + 2*128*24) * 4)

__global__ void __launch_bounds__(256) proj_kernel(
    const float* __restrict__ qin,
    const float* __restrict__ kin,
    const float* __restrict__ vin,
    const float* __restrict__ w,
    const float* __restrict__ bias)
{
    extern __shared__ __align__(16) unsigned smx[];
    unsigned (*As)[128][24] = reinterpret_cast<unsigned(*)[128][24]>(smx);
    unsigned (*Bs)[128][24] = reinterpret_cast<unsigned(*)[128][24]>(smx + 2*128*24);

    int which = blockIdx.z;
    const float* x  = (which == 0) ? qin : (which == 1) ? kin : vin;
    const float* W  = w + (size_t)which * E * E;
    const float* bv = bias + which * E;
    float* outp = (which == 0) ? g_q : (which == 1) ? g_k : g_v;

    int tid = threadIdx.x;
    int warp = tid >> 5, lane = tid & 31;
    int g = lane >> 2, tg = lane & 3;
    int wm = warp >> 2, wn = warp & 3;
    int m0 = blockIdx.y * 128, n0 = blockIdx.x * 128;

    int lr = tid >> 1;            // 0..127
    int lc = (tid & 1) * 8;       // 0 or 8

    float4 ra0, ra1, rb0, rb1;
    const float* aBase = x + (size_t)(m0 + lr) * E + lc;
    const float* bBase = W + (size_t)(n0 + lr) * E + lc;

    ra0 = *(const float4*)(aBase);  ra1 = *(const float4*)(aBase + 4);
    rb0 = *(const float4*)(bBase);  rb1 = *(const float4*)(bBase + 4);
    {
        unsigned* ap = &As[0][lr][lc];
        ap[0]=f2tf(ra0.x); ap[2]=f2tf(ra0.y); ap[4]=f2tf(ra0.z); ap[6]=f2tf(ra0.w);
        ap[1]=f2tf(ra1.x); ap[3]=f2tf(ra1.y); ap[5]=f2tf(ra1.z); ap[7]=f2tf(ra1.w);
        unsigned* bp = &Bs[0][lr][lc];
        bp[0]=f2tf(rb0.x); bp[2]=f2tf(rb0.y); bp[4]=f2tf(rb0.z); bp[6]=f2tf(rb0.w);
        bp[1]=f2tf(rb1.x); bp[3]=f2tf(rb1.y); bp[5]=f2tf(rb1.z); bp[7]=f2tf(rb1.w);
    }
    __syncthreads();

    float acc[4][4][4] = {};

    #pragma unroll 1
    for (int kt = 0; kt < 64; kt++) {
        int cur = kt & 1;
        if (kt < 63) {
            const float* ap = aBase + (kt+1)*16;
            const float* bp = bBase + (kt+1)*16;
            ra0 = *(const float4*)(ap);  ra1 = *(const float4*)(ap + 4);
            rb0 = *(const float4*)(bp);  rb1 = *(const float4*)(bp + 4);
        }

        #pragma unroll
        for (int kk = 0; kk < 2; kk++) {
            int kb = kk * 8 + 2*tg;
            unsigned a[4][4];
            #pragma unroll
            for (int mi = 0; mi < 4; mi++) {
                int r = wm*64 + mi*16 + g;
                uint2 lo = *(const uint2*)&As[cur][r][kb];
                uint2 hi = *(const uint2*)&As[cur][r+8][kb];
                a[mi][0] = lo.x; a[mi][1] = hi.x; a[mi][2] = lo.y; a[mi][3] = hi.y;
            }
            unsigned b[4][2];
            #pragma unroll
            for (int ni = 0; ni < 4; ni++) {
                int c = wn*32 + ni*8 + g;
                uint2 bb = *(const uint2*)&Bs[cur][c][kb];
                b[ni][0] = bb.x; b[ni][1] = bb.y;
            }
            #pragma unroll
            for (int mi = 0; mi < 4; mi++)
                #pragma unroll
                for (int ni = 0; ni < 4; ni++)
                    mma8(acc[mi][ni], a[mi][0], a[mi][1], a[mi][2], a[mi][3],
                         b[ni][0], b[ni][1]);
        }

        if (kt < 63) {
            int nxt = cur ^ 1;
            unsigned* ap = &As[nxt][lr][lc];
            ap[0]=f2tf(ra0.x); ap[2]=f2tf(ra0.y); ap[4]=f2tf(ra0.z); ap[6]=f2tf(ra0.w);
            ap[1]=f2tf(ra1.x); ap[3]=f2tf(ra1.y); ap[5]=f2tf(ra1.z); ap[7]=f2tf(ra1.w);
            unsigned* bp = &Bs[nxt][lr][lc];
            bp[0]=f2tf(rb0.x); bp[2]=f2tf(rb0.y); bp[4]=f2tf(rb0.z); bp[6]=f2tf(rb0.w);
            bp[1]=f2tf(rb1.x); bp[3]=f2tf(rb1.y); bp[5]=f2tf(rb1.z); bp[7]=f2tf(rb1.w);
            __syncthreads();
        }
    }

    #pragma unroll
    for (int mi = 0; mi < 4; mi++) {
        #pragma unroll
        for (int hf = 0; hf < 2; hf++) {
            int row = m0 + wm*64 + mi*16 + g + hf*8;
            int t = row >> 1, b = row & 1;
            #pragma unroll
            for (int ni = 0; ni < 4; ni++) {
                int col = n0 + wn*32 + ni*8 + tg*2;
                int h = col >> 6, d = col & 63;
                float2 o = { acc[mi][ni][hf*2+0] + bv[col],
                             acc[mi][ni][hf*2+1] + bv[col+1] };
                *(float2*)&outp[(size_t)(((b<<4) + h) * SQ + t) * HD + d] = o;
            }
        }
    }
}

// ===========================================================================
// Kernel 2: scores -> exp(s) + row sums.  t-tile 128, s-tile 128, paired LDS.
// Dyn smem: Qs[128][72] | Ks[2][128][72] | red_l[128][17]
// ===========================================================================
#define SC_SMEM_BYTES ((3*128*72 + 128*17) * 4)

__global__ void __launch_bounds__(256) scores_kernel(float* __restrict__ attn)
{
    extern __shared__ __align__(16) unsigned sm[];
    unsigned (*Qs)[72] = reinterpret_cast<unsigned(*)[72]>(sm);
    unsigned (*Ks)[128][72] = reinterpret_cast<unsigned(*)[128][72]>(sm + 128*72);
    float (*red_l)[17] = reinterpret_cast<float(*)[17]>(sm + 3*128*72);

    int tid = threadIdx.x;
    int warp = tid >> 5, lane = tid & 31;
    int g = lane >> 2, tg = lane & 3;
    int wm = warp >> 2, wn = warp & 3;
    int t0 = blockIdx.x * 128;
    int bh = blockIdx.y;

    const float* qb = g_q + (size_t)bh * SQ * HD;
    const float* kb = g_k + (size_t)bh * SQ * HD;

    int lrow = tid >> 4;          // 0..15
    int lcol = (tid & 15) * 4;    // 0..60
    int pb = (lcol & ~7) + ((lcol >> 2) & 1);   // interleaved base position

    // Load Q tile (resident)
    #pragma unroll
    for (int j = 0; j < 8; j++) {
        int r = j*16 + lrow;
        float4 a4 = *(const float4*)(qb + (size_t)(t0 + r) * HD + lcol);
        Qs[r][pb+0]=f2tf(a4.x); Qs[r][pb+2]=f2tf(a4.y);
        Qs[r][pb+4]=f2tf(a4.z); Qs[r][pb+6]=f2tf(a4.w);
    }
    // Load K tile 0
    float4 kr[8];
    #pragma unroll
    for (int j = 0; j < 8; j++)
        kr[j] = *(const float4*)(kb + (size_t)(j*16 + lrow) * HD + lcol);
    #pragma unroll
    for (int j = 0; j < 8; j++) {
        int r = j*16 + lrow;
        Ks[0][r][pb+0]=f2tf(kr[j].x); Ks[0][r][pb+2]=f2tf(kr[j].y);
        Ks[0][r][pb+4]=f2tf(kr[j].z); Ks[0][r][pb+6]=f2tf(kr[j].w);
    }
    __syncthreads();

    const float scale = 0.125f;
    float l[4][2];
    #pragma unroll
    for (int mi = 0; mi < 4; mi++) { l[mi][0] = 0.f; l[mi][1] = 0.f; }

    #pragma unroll 1
    for (int st = 0; st < 16; st++) {
        int cur = st & 1;
        if (st < 15) {
            const float* kp = kb + (size_t)(st+1) * 128 * HD;
            #pragma unroll
            for (int j = 0; j < 8; j++)
                kr[j] = *(const float4*)(kp + (size_t)(j*16 + lrow) * HD + lcol);
        }

        float c[4][4][4];
        #pragma unroll
        for (int mi = 0; mi < 4; mi++)
            #pragma unroll
            for (int ni = 0; ni < 4; ni++)
                #pragma unroll
                for (int q = 0; q < 4; q++) c[mi][ni][q] = 0.f;

        #pragma unroll
        for (int kk = 0; kk < 8; kk++) {
            int kb8 = kk * 8 + 2*tg;
            unsigned a[4][4];
            #pragma unroll
            for (int mi = 0; mi < 4; mi++) {
                int r = wm*64 + mi*16 + g;
                uint2 lo = *(const uint2*)&Qs[r][kb8];
                uint2 hi = *(const uint2*)&Qs[r+8][kb8];
                a[mi][0] = lo.x; a[mi][1] = hi.x; a[mi][2] = lo.y; a[mi][3] = hi.y;
            }
            unsigned b[4][2];
            #pragma unroll
            for (int ni = 0; ni < 4; ni++) {
                int cx = wn*32 + ni*8 + g;
                uint2 bb = *(const uint2*)&Ks[cur][cx][kb8];
                b[ni][0] = bb.x; b[ni][1] = bb.y;
            }
            #pragma unroll
            for (int mi = 0; mi < 4; mi++)
                #pragma unroll
                for (int ni = 0; ni < 4; ni++)
                    mma8(c[mi][ni], a[mi][0], a[mi][1], a[mi][2], a[mi][3],
                         b[ni][0], b[ni][1]);
        }

        // e = exp(scale*s); store; accumulate row sums
        #pragma unroll
        for (int mi = 0; mi < 4; mi++) {
            #pragma unroll
            for (int hf = 0; hf < 2; hf++) {
                int tr = t0 + wm*64 + mi*16 + g + hf*8;
                float* pr = attn + ((size_t)bh*SQ + tr)*SQ + st*128 + wn*32 + tg*2;
                float lacc = 0.f;
                #pragma unroll
                for (int ni = 0; ni < 4; ni++) {
                    float e0 = __expf(c[mi][ni][hf*2+0] * scale);
                    float e1 = __expf(c[mi][ni][hf*2+1] * scale);
                    *(float2*)(pr + ni*8) = make_float2(e0, e1);
                    lacc += e0 + e1;
                }
                l[mi][hf] += lacc;
            }
        }

        if (st < 15) {
            int nxt = cur ^ 1;
            #pragma unroll
            for (int j = 0; j < 8; j++) {
                int r = j*16 + lrow;
                Ks[nxt][r][pb+0]=f2tf(kr[j].x); Ks[nxt][r][pb+2]=f2tf(kr[j].y);
                Ks[nxt][r][pb+4]=f2tf(kr[j].z); Ks[nxt][r][pb+6]=f2tf(kr[j].w);
            }
            __syncthreads();
        }
    }

    #pragma unroll
    for (int mi = 0; mi < 4; mi++)
        #pragma unroll
        for (int hf = 0; hf < 2; hf++) {
            int tr = wm*64 + mi*16 + g + hf*8;
            red_l[tr][wn*4 + tg] = l[mi][hf];
        }
    __syncthreads();
    if (tid < 128) {
        float L = 0.f;
        #pragma unroll
        for (int p = 0; p < 16; p++) L += red_l[tid][p];
        g_rowinv[bh*SQ + t0 + tid] = 1.0f / L;
    }
}

// ===========================================================================
// Kernel 3: normalize + write probs + PV MMA.  Paired LDS.
// Dyn smem: Ps[2][128][136] | Vs[2][64][136] | sinv[128]
// Ps: [t][s-interleaved]; Vs: [d][s-interleaved]
// ===========================================================================
#define PV_SMEM_BYTES ((2*128*136 + 2*64*136 + 128) * 4)

__global__ void __launch_bounds__(256) pv_kernel(float* __restrict__ attn)
{
    extern __shared__ __align__(16) unsigned sm[];
    unsigned (*Ps)[128][136] = reinterpret_cast<unsigned(*)[128][136]>(sm);
    unsigned (*Vs)[64][136]  = reinterpret_cast<unsigned(*)[64][136]>(sm + 2*128*136);
    float* sinv = (float*)(sm + 2*128*136 + 2*64*136);

    int tid = threadIdx.x;
    int warp = tid >> 5, lane = tid & 31;
    int g = lane >> 2, tg = lane & 3;
    int wm = warp >> 1, wn = warp & 1;   // wm 0..3 (M), wn 0..1 (N)
    int t0 = blockIdx.x * 128;
    int bh = blockIdx.y;
    int b = bh >> 4, h = bh & 15;

    const float* vb = g_v + (size_t)bh * SQ * HD;
    float* pb0 = attn + ((size_t)bh*SQ + t0) * SQ;

    if (tid < 128) sinv[tid] = g_rowinv[bh*SQ + t0 + tid];
    __syncthreads();

    // P staging geometry: row = j*8 + (tid>>5), cols (tid&31)*4
    int prow_lo = tid >> 5;
    int pcol = (tid & 31) * 4;
    int ppb = (pcol & ~7) + ((pcol >> 2) & 1);
    // V staging geometry: s = j*16 + (tid>>4), d0 = (tid&15)*4
    int vs_lo = tid >> 4;
    int vd0 = (tid & 15) * 4;

    float4 pr[16], vr[8];

    // prologue: step 0
    #pragma unroll
    for (int j = 0; j < 16; j++)
        pr[j] = *(const float4*)(pb0 + (size_t)(j*8 + prow_lo) * SQ + pcol);
    #pragma unroll
    for (int j = 0; j < 8; j++)
        vr[j] = *(const float4*)(vb + (size_t)(j*16 + vs_lo) * HD + vd0);
    #pragma unroll
    for (int j = 0; j < 16; j++) {
        int row = j*8 + prow_lo;
        float inv = sinv[row];
        float4 p = pr[j];
        p.x *= inv; p.y *= inv; p.z *= inv; p.w *= inv;
        *(float4*)(pb0 + (size_t)row * SQ + pcol) = p;
        Ps[0][row][ppb+0]=f2tf(p.x); Ps[0][row][ppb+2]=f2tf(p.y);
        Ps[0][row][ppb+4]=f2tf(p.z); Ps[0][row][ppb+6]=f2tf(p.w);
    }
    #pragma unroll
    for (int j = 0; j < 8; j++) {
        int s = j*16 + vs_lo;
        int ps = (s & ~7) + 2*(s&3) + ((s>>2)&1);
        Vs[0][vd0+0][ps]=f2tf(vr[j].x); Vs[0][vd0+1][ps]=f2tf(vr[j].y);
        Vs[0][vd0+2][ps]=f2tf(vr[j].z); Vs[0][vd0+3][ps]=f2tf(vr[j].w);
    }
    __syncthreads();

    float acc[2][4][4] = {};

    #pragma unroll 1
    for (int st = 0; st < 16; st++) {
        int cur = st & 1;
        if (st < 15) {
            const float* pp = pb0 + (st+1)*128;
            const float* vp = vb + (size_t)(st+1)*128*HD;
            #pragma unroll
            for (int j = 0; j < 16; j++)
                pr[j] = *(const float4*)(pp + (size_t)(j*8 + prow_lo) * SQ + pcol);
            #pragma unroll
            for (int j = 0; j < 8; j++)
                vr[j] = *(const float4*)(vp + (size_t)(j*16 + vs_lo) * HD + vd0);
        }

        #pragma unroll
        for (int kk = 0; kk < 16; kk++) {
            int kb8 = kk * 8 + 2*tg;
            unsigned a[2][4];
            #pragma unroll
            for (int mi = 0; mi < 2; mi++) {
                int r = wm*32 + mi*16 + g;
                uint2 lo = *(const uint2*)&Ps[cur][r][kb8];
                uint2 hi = *(const uint2*)&Ps[cur][r+8][kb8];
                a[mi][0] = lo.x; a[mi][1] = hi.x; a[mi][2] = lo.y; a[mi][3] = hi.y;
            }
            unsigned bb[4][2];
            #pragma unroll
            for (int ni = 0; ni < 4; ni++) {
                int cx = wn*32 + ni*8 + g;
                uint2 bv2 = *(const uint2*)&Vs[cur][cx][kb8];
                bb[ni][0] = bv2.x; bb[ni][1] = bv2.y;
            }
            #pragma unroll
            for (int mi = 0; mi < 2; mi++)
                #pragma unroll
                for (int ni = 0; ni < 4; ni++)
                    mma8(acc[mi][ni], a[mi][0], a[mi][1], a[mi][2], a[mi][3],
                         bb[ni][0], bb[ni][1]);
        }

        if (st < 15) {
            int nxt = cur ^ 1;
            #pragma unroll
            for (int j = 0; j < 16; j++) {
                int row = j*8 + prow_lo;
                float inv = sinv[row];
                float4 p = pr[j];
                p.x *= inv; p.y *= inv; p.z *= inv; p.w *= inv;
                *(float4*)(pb0 + (size_t)row * SQ + (st+1)*128 + pcol) = p;
                Ps[nxt][row][ppb+0]=f2tf(p.x); Ps[nxt][row][ppb+2]=f2tf(p.y);
                Ps[nxt][row][ppb+4]=f2tf(p.z); Ps[nxt][row][ppb+6]=f2tf(p.w);
            }
            #pragma unroll
            for (int j = 0; j < 8; j++) {
                int s = j*16 + vs_lo;
                int ps = (s & ~7) + 2*(s&3) + ((s>>2)&1);
                Vs[nxt][vd0+0][ps]=f2tf(vr[j].x); Vs[nxt][vd0+1][ps]=f2tf(vr[j].y);
                Vs[nxt][vd0+2][ps]=f2tf(vr[j].z); Vs[nxt][vd0+3][ps]=f2tf(vr[j].w);
            }
            __syncthreads();
        }
    }

    #pragma unroll
    for (int mi = 0; mi < 2; mi++)
        #pragma unroll
        for (int hf = 0; hf < 2; hf++) {
            int t = t0 + wm*32 + mi*16 + g + hf*8;
            #pragma unroll
            for (int ni = 0; ni < 4; ni++) {
                int d = wn*32 + ni*8 + tg*2;
                float2 o = { acc[mi][ni][hf*2+0], acc[mi][ni][hf*2+1] };
                *(float2*)&g_ctx[(size_t)(t*BS + b)*E + h*64 + d] = o;
            }
        }
}

// ===========================================================================
// Kernel 4: out projection (pipelined 128x128 tf32 GEMM, paired LDS).
// ===========================================================================
__global__ void __launch_bounds__(256) outproj_kernel(
    const float* __restrict__ w,
    const float* __restrict__ bias,
    float* __restrict__ out)
{
    extern __shared__ __align__(16) unsigned smx[];
    unsigned (*As)[128][24] = reinterpret_cast<unsigned(*)[128][24]>(smx);
    unsigned (*Bs)[128][24] = reinterpret_cast<unsigned(*)[128][24]>(smx + 2*128*24);

    int tid = threadIdx.x;
    int warp = tid >> 5, lane = tid & 31;
    int g = lane >> 2, tg = lane & 3;
    int wm = warp >> 2, wn = warp & 3;
    int m0 = blockIdx.y * 128, n0 = blockIdx.x * 128;

    int lr = tid >> 1;
    int lc = (tid & 1) * 8;

    float4 ra0, ra1, rb0, rb1;
    const float* aBase = g_ctx + (size_t)(m0 + lr) * E + lc;
    const float* bBase = w + (size_t)(n0 + lr) * E + lc;

    ra0 = *(const float4*)(aBase);  ra1 = *(const float4*)(aBase + 4);
    rb0 = *(const float4*)(bBase);  rb1 = *(const float4*)(bBase + 4);
    {
        unsigned* ap = &As[0][lr][lc];
        ap[0]=f2tf(ra0.x); ap[2]=f2tf(ra0.y); ap[4]=f2tf(ra0.z); ap[6]=f2tf(ra0.w);
        ap[1]=f2tf(ra1.x); ap[3]=f2tf(ra1.y); ap[5]=f2tf(ra1.z); ap[7]=f2tf(ra1.w);
        unsigned* bp = &Bs[0][lr][lc];
        bp[0]=f2tf(rb0.x); bp[2]=f2tf(rb0.y); bp[4]=f2tf(rb0.z); bp[6]=f2tf(rb0.w);
        bp[1]=f2tf(rb1.x); bp[3]=f2tf(rb1.y); bp[5]=f2tf(rb1.z); bp[7]=f2tf(rb1.w);
    }
    __syncthreads();

    float acc[4][4][4] = {};

    #pragma unroll 1
    for (int kt = 0; kt < 64; kt++) {
        int cur = kt & 1;
        if (kt < 63) {
            const float* ap = aBase + (kt+1)*16;
            const float* bp = bBase + (kt+1)*16;
            ra0 = *(const float4*)(ap);  ra1 = *(const float4*)(ap + 4);
            rb0 = *(const float4*)(bp);  rb1 = *(const float4*)(bp + 4);
        }

        #pragma unroll
        for (int kk = 0; kk < 2; kk++) {
            int kb = kk * 8 + 2*tg;
            unsigned a[4][4];
            #pragma unroll
            for (int mi = 0; mi < 4; mi++) {
                int r = wm*64 + mi*16 + g;
                uint2 lo = *(const uint2*)&As[cur][r][kb];
                uint2 hi = *(const uint2*)&As[cur][r+8][kb];
                a[mi][0] = lo.x; a[mi][1] = hi.x; a[mi][2] = lo.y; a[mi][3] = hi.y;
            }
            unsigned b[4][2];
            #pragma unroll
            for (int ni = 0; ni < 4; ni++) {
                int c = wn*32 + ni*8 + g;
                uint2 bb = *(const uint2*)&Bs[cur][c][kb];
                b[ni][0] = bb.x; b[ni][1] = bb.y;
            }
            #pragma unroll
            for (int mi = 0; mi < 4; mi++)
                #pragma unroll
                for (int ni = 0; ni < 4; ni++)
                    mma8(acc[mi][ni], a[mi][0], a[mi][1], a[mi][2], a[mi][3],
                         b[ni][0], b[ni][1]);
        }

        if (kt < 63) {
            int nxt = cur ^ 1;
            unsigned* ap = &As[nxt][lr][lc];
            ap[0]=f2tf(ra0.x); ap[2]=f2tf(ra0.y); ap[4]=f2tf(ra0.z); ap[6]=f2tf(ra0.w);
            ap[1]=f2tf(ra1.x); ap[3]=f2tf(ra1.y); ap[5]=f2tf(ra1.z); ap[7]=f2tf(ra1.w);
            unsigned* bp = &Bs[nxt][lr][lc];
            bp[0]=f2tf(rb0.x); bp[2]=f2tf(rb0.y); bp[4]=f2tf(rb0.z); bp[6]=f2tf(rb0.w);
            bp[1]=f2tf(rb1.x); bp[3]=f2tf(rb1.y); bp[5]=f2tf(rb1.z); bp[7]=f2tf(rb1.w);
            __syncthreads();
        }
    }

    #pragma unroll
    for (int mi = 0; mi < 4; mi++) {
        #pragma unroll
        for (int hf = 0; hf < 2; hf++) {
            int row = m0 + wm*64 + mi*16 + g + hf*8;
            #pragma unroll
            for (int ni = 0; ni < 4; ni++) {
                int col = n0 + wn*32 + ni*8 + tg*2;
                float2 o = { acc[mi][ni][hf*2+0] + bias[col],
                             acc[mi][ni][hf*2+1] + bias[col+1] };
                *(float2*)&out[(size_t)row * E + col] = o;
            }
        }
    }
}

// ---------------------------------------------------------------------------
extern "C" void kernel_launch(void* const* d_in, const int* in_sizes, int n_in,
                              void* d_out, int out_size)
{
    const float* q   = (const float*)d_in[0];
    const float* k   = (const float*)d_in[1];
    const float* v   = (const float*)d_in[2];
    const float* inw = (const float*)d_in[3];
    const float* inb = (const float*)d_in[4];
    const float* ow  = (const float*)d_in[5];
    const float* ob  = (const float*)d_in[6];

    float* out  = (float*)d_out;
    float* attn = out + OUT0;

    cudaFuncSetAttribute(proj_kernel,    cudaFuncAttributeMaxDynamicSharedMemorySize, PR_SMEM_BYTES);
    cudaFuncSetAttribute(outproj_kernel, cudaFuncAttributeMaxDynamicSharedMemorySize, PR_SMEM_BYTES);
    cudaFuncSetAttribute(scores_kernel,  cudaFuncAttributeMaxDynamicSharedMemorySize, SC_SMEM_BYTES);
    cudaFuncSetAttribute(pv_kernel,      cudaFuncAttributeMaxDynamicSharedMemorySize, PV_SMEM_BYTES);

    proj_kernel<<<dim3(E/128, TB/128, 3), 256, PR_SMEM_BYTES>>>(q, k, v, inw, inb);
    scores_kernel<<<dim3(SQ/128, BH), 256, SC_SMEM_BYTES>>>(attn);
    pv_kernel<<<dim3(SQ/128, BH), 256, PV_SMEM_BYTES>>>(attn);
    outproj_kernel<<<dim3(E/128, TB/128), 256, PR_SMEM_BYTES>>>(ow, ob, out);
}

// round 14
// speedup vs baseline: 1.2177x; 1.2177x over previous
#include <cuda_runtime.h>
#include <math.h>

// Problem constants
#define E   1024
#define NH  16
#define HD  64
#define SQ  2048
#define BS  2
#define TB  (SQ*BS)       // 4096
#define BH  (BS*NH)       // 32
#define OUT0 ((size_t)SQ*BS*E)

// Scratch
__device__ float g_q[BH*SQ*HD];
__device__ float g_k[BH*SQ*HD];
__device__ float g_v[BH*SQ*HD];
__device__ float g_ctx[TB*E];
__device__ float g_rowinv[BH*SQ];

// ---------------------------------------------------------------------------
// tf32 helpers
// ---------------------------------------------------------------------------
__device__ __forceinline__ unsigned f2tf(float f) {
    unsigned r;
    asm("cvt.rna.tf32.f32 %0, %1;" : "=r"(r) : "f"(f));
    return r;
}

__device__ __forceinline__ void mma8(float* c,
                                     unsigned a0, unsigned a1, unsigned a2, unsigned a3,
                                     unsigned b0, unsigned b1) {
    asm volatile(
        "mma.sync.aligned.m16n8k8.row.col.f32.tf32.tf32.f32 "
        "{%0,%1,%2,%3}, {%4,%5,%6,%7}, {%8,%9}, {%0,%1,%2,%3};\n"
        : "+f"(c[0]), "+f"(c[1]), "+f"(c[2]), "+f"(c[3])
        : "r"(a0), "r"(a1), "r"(a2), "r"(a3), "r"(b0), "r"(b1));
}

// ===========================================================================
// Kernel 1: QKV projection (pipelined 128x128 tf32 GEMM, paired LDS). [r12]
// Dyn smem: As[2][128][24] | Bs[2][128][24]
// ===========================================================================
#define PR_SMEM_BYTES ((2*128*24 + 2*128*24) * 4)

__global__ void __launch_bounds__(256) proj_kernel(
    const float* __restrict__ qin,
    const float* __restrict__ kin,
    const float* __restrict__ vin,
    const float* __restrict__ w,
    const float* __restrict__ bias)
{
    extern __shared__ __align__(16) unsigned smx[];
    unsigned (*As)[128][24] = reinterpret_cast<unsigned(*)[128][24]>(smx);
    unsigned (*Bs)[128][24] = reinterpret_cast<unsigned(*)[128][24]>(smx + 2*128*24);

    int which = blockIdx.z;
    const float* x  = (which == 0) ? qin : (which == 1) ? kin : vin;
    const float* W  = w + (size_t)which * E * E;
    const float* bv = bias + which * E;
    float* outp = (which == 0) ? g_q : (which == 1) ? g_k : g_v;

    int tid = threadIdx.x;
    int warp = tid >> 5, lane = tid & 31;
    int g = lane >> 2, tg = lane & 3;
    int wm = warp >> 2, wn = warp & 3;
    int m0 = blockIdx.y * 128, n0 = blockIdx.x * 128;

    int lr = tid >> 1;
    int lc = (tid & 1) * 8;

    float4 ra0, ra1, rb0, rb1;
    const float* aBase = x + (size_t)(m0 + lr) * E + lc;
    const float* bBase = W + (size_t)(n0 + lr) * E + lc;

    ra0 = *(const float4*)(aBase);  ra1 = *(const float4*)(aBase + 4);
    rb0 = *(const float4*)(bBase);  rb1 = *(const float4*)(bBase + 4);
    {
        unsigned* ap = &As[0][lr][lc];
        ap[0]=f2tf(ra0.x); ap[2]=f2tf(ra0.y); ap[4]=f2tf(ra0.z); ap[6]=f2tf(ra0.w);
        ap[1]=f2tf(ra1.x); ap[3]=f2tf(ra1.y); ap[5]=f2tf(ra1.z); ap[7]=f2tf(ra1.w);
        unsigned* bp = &Bs[0][lr][lc];
        bp[0]=f2tf(rb0.x); bp[2]=f2tf(rb0.y); bp[4]=f2tf(rb0.z); bp[6]=f2tf(rb0.w);
        bp[1]=f2tf(rb1.x); bp[3]=f2tf(rb1.y); bp[5]=f2tf(rb1.z); bp[7]=f2tf(rb1.w);
    }
    __syncthreads();

    float acc[4][4][4] = {};

    #pragma unroll 1
    for (int kt = 0; kt < 64; kt++) {
        int cur = kt & 1;
        if (kt < 63) {
            const float* ap = aBase + (kt+1)*16;
            const float* bp = bBase + (kt+1)*16;
            ra0 = *(const float4*)(ap);  ra1 = *(const float4*)(ap + 4);
            rb0 = *(const float4*)(bp);  rb1 = *(const float4*)(bp + 4);
        }

        #pragma unroll
        for (int kk = 0; kk < 2; kk++) {
            int kb = kk * 8 + 2*tg;
            unsigned a[4][4];
            #pragma unroll
            for (int mi = 0; mi < 4; mi++) {
                int r = wm*64 + mi*16 + g;
                uint2 lo = *(const uint2*)&As[cur][r][kb];
                uint2 hi = *(const uint2*)&As[cur][r+8][kb];
                a[mi][0] = lo.x; a[mi][1] = hi.x; a[mi][2] = lo.y; a[mi][3] = hi.y;
            }
            unsigned b[4][2];
            #pragma unroll
            for (int ni = 0; ni < 4; ni++) {
                int c = wn*32 + ni*8 + g;
                uint2 bb = *(const uint2*)&Bs[cur][c][kb];
                b[ni][0] = bb.x; b[ni][1] = bb.y;
            }
            #pragma unroll
            for (int mi = 0; mi < 4; mi++)
                #pragma unroll
                for (int ni = 0; ni < 4; ni++)
                    mma8(acc[mi][ni], a[mi][0], a[mi][1], a[mi][2], a[mi][3],
                         b[ni][0], b[ni][1]);
        }

        if (kt < 63) {
            int nxt = cur ^ 1;
            unsigned* ap = &As[nxt][lr][lc];
            ap[0]=f2tf(ra0.x); ap[2]=f2tf(ra0.y); ap[4]=f2tf(ra0.z); ap[6]=f2tf(ra0.w);
            ap[1]=f2tf(ra1.x); ap[3]=f2tf(ra1.y); ap[5]=f2tf(ra1.z); ap[7]=f2tf(ra1.w);
            unsigned* bp = &Bs[nxt][lr][lc];
            bp[0]=f2tf(rb0.x); bp[2]=f2tf(rb0.y); bp[4]=f2tf(rb0.z); bp[6]=f2tf(rb0.w);
            bp[1]=f2tf(rb1.x); bp[3]=f2tf(rb1.y); bp[5]=f2tf(rb1.z); bp[7]=f2tf(rb1.w);
            __syncthreads();
        }
    }

    #pragma unroll
    for (int mi = 0; mi < 4; mi++) {
        #pragma unroll
        for (int hf = 0; hf < 2; hf++) {
            int row = m0 + wm*64 + mi*16 + g + hf*8;
            int t = row >> 1, b = row & 1;
            #pragma unroll
            for (int ni = 0; ni < 4; ni++) {
                int col = n0 + wn*32 + ni*8 + tg*2;
                int h = col >> 6, d = col & 63;
                float2 o = { acc[mi][ni][hf*2+0] + bv[col],
                             acc[mi][ni][hf*2+1] + bv[col+1] };
                *(float2*)&outp[(size_t)(((b<<4) + h) * SQ + t) * HD + d] = o;
            }
        }
    }
}

// ===========================================================================
// Kernel 2: scores -> exp(s) + row sums. [r9 verbatim]
// Dyn smem: Qs[128][68] | Ks[2][128][68] | red_l[128][17]
// ===========================================================================
#define SC_SMEM_BYTES ((3*128*68 + 128*17) * 4)

__global__ void __launch_bounds__(256) scores_kernel(float* __restrict__ attn)
{
    extern __shared__ __align__(16) unsigned sm[];
    unsigned (*Qs)[68] = reinterpret_cast<unsigned(*)[68]>(sm);
    unsigned (*Ks)[128][68] = reinterpret_cast<unsigned(*)[128][68]>(sm + 128*68);
    float (*red_l)[17] = reinterpret_cast<float(*)[17]>(sm + 3*128*68);

    int tid = threadIdx.x;
    int warp = tid >> 5, lane = tid & 31;
    int g = lane >> 2, tg = lane & 3;
    int wm = warp >> 2, wn = warp & 3;
    int t0 = blockIdx.x * 128;
    int bh = blockIdx.y;

    const float* qb = g_q + (size_t)bh * SQ * HD;
    const float* kb = g_k + (size_t)bh * SQ * HD;

    int lrow = tid >> 4;
    int lcol = (tid & 15) * 4;

    #pragma unroll
    for (int j = 0; j < 8; j++) {
        int r = j*16 + lrow;
        float4 a4 = *(const float4*)(qb + (size_t)(t0 + r) * HD + lcol);
        uint4 t4 = { f2tf(a4.x), f2tf(a4.y), f2tf(a4.z), f2tf(a4.w) };
        *(uint4*)&Qs[r][lcol] = t4;
    }
    float4 kr[8];
    #pragma unroll
    for (int j = 0; j < 8; j++)
        kr[j] = *(const float4*)(kb + (size_t)(j*16 + lrow) * HD + lcol);
    #pragma unroll
    for (int j = 0; j < 8; j++) {
        uint4 t4 = { f2tf(kr[j].x), f2tf(kr[j].y), f2tf(kr[j].z), f2tf(kr[j].w) };
        *(uint4*)&Ks[0][j*16 + lrow][lcol] = t4;
    }
    __syncthreads();

    const float scale = 0.125f;
    float l[4][2];
    #pragma unroll
    for (int mi = 0; mi < 4; mi++) { l[mi][0] = 0.f; l[mi][1] = 0.f; }

    #pragma unroll 1
    for (int st = 0; st < 16; st++) {
        int cur = st & 1;
        if (st < 15) {
            const float* kp = kb + (size_t)(st+1) * 128 * HD;
            #pragma unroll
            for (int j = 0; j < 8; j++)
                kr[j] = *(const float4*)(kp + (size_t)(j*16 + lrow) * HD + lcol);
        }

        float c[4][4][4];
        #pragma unroll
        for (int mi = 0; mi < 4; mi++)
            #pragma unroll
            for (int ni = 0; ni < 4; ni++)
                #pragma unroll
                for (int q = 0; q < 4; q++) c[mi][ni][q] = 0.f;

        #pragma unroll
        for (int kk = 0; kk < 8; kk++) {
            int kb8 = kk * 8;
            unsigned a[4][4];
            #pragma unroll
            for (int mi = 0; mi < 4; mi++) {
                int r = wm*64 + mi*16 + g;
                a[mi][0] = Qs[r][kb8+tg];    a[mi][1] = Qs[r+8][kb8+tg];
                a[mi][2] = Qs[r][kb8+tg+4];  a[mi][3] = Qs[r+8][kb8+tg+4];
            }
            unsigned b[4][2];
            #pragma unroll
            for (int ni = 0; ni < 4; ni++) {
                int cx = wn*32 + ni*8 + g;
                b[ni][0] = Ks[cur][cx][kb8+tg];
                b[ni][1] = Ks[cur][cx][kb8+tg+4];
            }
            #pragma unroll
            for (int mi = 0; mi < 4; mi++)
                #pragma unroll
                for (int ni = 0; ni < 4; ni++)
                    mma8(c[mi][ni], a[mi][0], a[mi][1], a[mi][2], a[mi][3],
                         b[ni][0], b[ni][1]);
        }

        #pragma unroll
        for (int mi = 0; mi < 4; mi++) {
            #pragma unroll
            for (int hf = 0; hf < 2; hf++) {
                int tr = t0 + wm*64 + mi*16 + g + hf*8;
                float* pr = attn + ((size_t)bh*SQ + tr)*SQ + st*128 + wn*32 + tg*2;
                float lacc = 0.f;
                #pragma unroll
                for (int ni = 0; ni < 4; ni++) {
                    float e0 = __expf(c[mi][ni][hf*2+0] * scale);
                    float e1 = __expf(c[mi][ni][hf*2+1] * scale);
                    *(float2*)(pr + ni*8) = make_float2(e0, e1);
                    lacc += e0 + e1;
                }
                l[mi][hf] += lacc;
            }
        }

        if (st < 15) {
            int nxt = cur ^ 1;
            #pragma unroll
            for (int j = 0; j < 8; j++) {
                uint4 t4 = { f2tf(kr[j].x), f2tf(kr[j].y), f2tf(kr[j].z), f2tf(kr[j].w) };
                *(uint4*)&Ks[nxt][j*16 + lrow][lcol] = t4;
            }
            __syncthreads();
        }
    }

    #pragma unroll
    for (int mi = 0; mi < 4; mi++)
        #pragma unroll
        for (int hf = 0; hf < 2; hf++) {
            int tr = wm*64 + mi*16 + g + hf*8;
            red_l[tr][wn*4 + tg] = l[mi][hf];
        }
    __syncthreads();
    if (tid < 128) {
        float L = 0.f;
        #pragma unroll
        for (int p = 0; p < 16; p++) L += red_l[tid][p];
        g_rowinv[bh*SQ + t0 + tid] = 1.0f / L;
    }
}

// ===========================================================================
// Kernel 3: normalize + write probs + PV MMA. [r9 verbatim]
// Dyn smem: Ps[2][128][132] | Vs[2][128][72] | sinv[128]
// ===========================================================================
#define PV_SMEM_BYTES ((2*128*132 + 2*128*72 + 128) * 4)

__global__ void __launch_bounds__(256) pv_kernel(float* __restrict__ attn)
{
    extern __shared__ __align__(16) unsigned sm[];
    unsigned (*Ps)[128][132] = reinterpret_cast<unsigned(*)[128][132]>(sm);
    unsigned (*Vs)[128][72]  = reinterpret_cast<unsigned(*)[128][72]>(sm + 2*128*132);
    float* sinv = (float*)(sm + 2*128*132 + 2*128*72);

    int tid = threadIdx.x;
    int warp = tid >> 5, lane = tid & 31;
    int g = lane >> 2, tg = lane & 3;
    int wm = warp >> 1, wn = warp & 1;
    int t0 = blockIdx.x * 128;
    int bh = blockIdx.y;
    int b = bh >> 4, h = bh & 15;

    const float* vb = g_v + (size_t)bh * SQ * HD;
    float* pb0 = attn + ((size_t)bh*SQ + t0) * SQ;

    if (tid < 128) sinv[tid] = g_rowinv[bh*SQ + t0 + tid];
    __syncthreads();

    float4 pr[16], vr[8];

    #pragma unroll
    for (int j = 0; j < 16; j++)
        pr[j] = *(const float4*)(pb0 + (size_t)(j*8 + (tid>>5)) * SQ + (tid&31)*4);
    #pragma unroll
    for (int j = 0; j < 8; j++)
        vr[j] = *(const float4*)(vb + (size_t)(j*16 + (tid>>4)) * HD + (tid&15)*4);
    #pragma unroll
    for (int j = 0; j < 16; j++) {
        int row = j*8 + (tid>>5);
        float inv = sinv[row];
        float4 p = pr[j];
        p.x *= inv; p.y *= inv; p.z *= inv; p.w *= inv;
        *(float4*)(pb0 + (size_t)row * SQ + (tid&31)*4) = p;
        uint4 t4 = { f2tf(p.x), f2tf(p.y), f2tf(p.z), f2tf(p.w) };
        *(uint4*)&Ps[0][row][(tid&31)*4] = t4;
    }
    #pragma unroll
    for (int j = 0; j < 8; j++) {
        uint4 t4 = { f2tf(vr[j].x), f2tf(vr[j].y), f2tf(vr[j].z), f2tf(vr[j].w) };
        *(uint4*)&Vs[0][j*16 + (tid>>4)][(tid&15)*4] = t4;
    }
    __syncthreads();

    float acc[2][4][4] = {};

    #pragma unroll 1
    for (int st = 0; st < 16; st++) {
        int cur = st & 1;
        if (st < 15) {
            const float* pp = pb0 + (st+1)*128;
            const float* vp = vb + (size_t)(st+1)*128*HD;
            #pragma unroll
            for (int j = 0; j < 16; j++)
                pr[j] = *(const float4*)(pp + (size_t)(j*8 + (tid>>5)) * SQ + (tid&31)*4);
            #pragma unroll
            for (int j = 0; j < 8; j++)
                vr[j] = *(const float4*)(vp + (size_t)(j*16 + (tid>>4)) * HD + (tid&15)*4);
        }

        #pragma unroll
        for (int kk = 0; kk < 16; kk++) {
            int kb8 = kk * 8;
            unsigned a[2][4];
            #pragma unroll
            for (int mi = 0; mi < 2; mi++) {
                int r = wm*32 + mi*16 + g;
                a[mi][0] = Ps[cur][r][kb8+tg];    a[mi][1] = Ps[cur][r+8][kb8+tg];
                a[mi][2] = Ps[cur][r][kb8+tg+4];  a[mi][3] = Ps[cur][r+8][kb8+tg+4];
            }
            unsigned bb[4][2];
            #pragma unroll
            for (int ni = 0; ni < 4; ni++) {
                int cx = wn*32 + ni*8 + g;
                bb[ni][0] = Vs[cur][kb8+tg][cx];
                bb[ni][1] = Vs[cur][kb8+tg+4][cx];
            }
            #pragma unroll
            for (int mi = 0; mi < 2; mi++)
                #pragma unroll
                for (int ni = 0; ni < 4; ni++)
                    mma8(acc[mi][ni], a[mi][0], a[mi][1], a[mi][2], a[mi][3],
                         bb[ni][0], bb[ni][1]);
        }

        if (st < 15) {
            int nxt = cur ^ 1;
            #pragma unroll
            for (int j = 0; j < 16; j++) {
                int row = j*8 + (tid>>5);
                float inv = sinv[row];
                float4 p = pr[j];
                p.x *= inv; p.y *= inv; p.z *= inv; p.w *= inv;
                *(float4*)(pb0 + (size_t)row * SQ + (st+1)*128 + (tid&31)*4) = p;
                uint4 t4 = { f2tf(p.x), f2tf(p.y), f2tf(p.z), f2tf(p.w) };
                *(uint4*)&Ps[nxt][row][(tid&31)*4] = t4;
            }
            #pragma unroll
            for (int j = 0; j < 8; j++) {
                uint4 t4 = { f2tf(vr[j].x), f2tf(vr[j].y), f2tf(vr[j].z), f2tf(vr[j].w) };
                *(uint4*)&Vs[nxt][j*16 + (tid>>4)][(tid&15)*4] = t4;
            }
            __syncthreads();
        }
    }

    #pragma unroll
    for (int mi = 0; mi < 2; mi++)
        #pragma unroll
        for (int hf = 0; hf < 2; hf++) {
            int t = t0 + wm*32 + mi*16 + g + hf*8;
            #pragma unroll
            for (int ni = 0; ni < 4; ni++) {
                int d = wn*32 + ni*8 + tg*2;
                float2 o = { acc[mi][ni][hf*2+0], acc[mi][ni][hf*2+1] };
                *(float2*)&g_ctx[(size_t)(t*BS + b)*E + h*64 + d] = o;
            }
        }
}

// ===========================================================================
// Kernel 4: out projection (pipelined 128x128 tf32 GEMM, paired LDS). [r12]
// ===========================================================================
__global__ void __launch_bounds__(256) outproj_kernel(
    const float* __restrict__ w,
    const float* __restrict__ bias,
    float* __restrict__ out)
{
    extern __shared__ __align__(16) unsigned smx[];
    unsigned (*As)[128][24] = reinterpret_cast<unsigned(*)[128][24]>(smx);
    unsigned (*Bs)[128][24] = reinterpret_cast<unsigned(*)[128][24]>(smx + 2*128*24);

    int tid = threadIdx.x;
    int warp = tid >> 5, lane = tid & 31;
    int g = lane >> 2, tg = lane & 3;
    int wm = warp >> 2, wn = warp & 3;
    int m0 = blockIdx.y * 128, n0 = blockIdx.x * 128;

    int lr = tid >> 1;
    int lc = (tid & 1) * 8;

    float4 ra0, ra1, rb0, rb1;
    const float* aBase = g_ctx + (size_t)(m0 + lr) * E + lc;
    const float* bBase = w + (size_t)(n0 + lr) * E + lc;

    ra0 = *(const float4*)(aBase);  ra1 = *(const float4*)(aBase + 4);
    rb0 = *(const float4*)(bBase);  rb1 = *(const float4*)(bBase + 4);
    {
        unsigned* ap = &As[0][lr][lc];
        ap[0]=f2tf(ra0.x); ap[2]=f2tf(ra0.y); ap[4]=f2tf(ra0.z); ap[6]=f2tf(ra0.w);
        ap[1]=f2tf(ra1.x); ap[3]=f2tf(ra1.y); ap[5]=f2tf(ra1.z); ap[7]=f2tf(ra1.w);
        unsigned* bp = &Bs[0][lr][lc];
        bp[0]=f2tf(rb0.x); bp[2]=f2tf(rb0.y); bp[4]=f2tf(rb0.z); bp[6]=f2tf(rb0.w);
        bp[1]=f2tf(rb1.x); bp[3]=f2tf(rb1.y); bp[5]=f2tf(rb1.z); bp[7]=f2tf(rb1.w);
    }
    __syncthreads();

    float acc[4][4][4] = {};

    #pragma unroll 1
    for (int kt = 0; kt < 64; kt++) {
        int cur = kt & 1;
        if (kt < 63) {
            const float* ap = aBase + (kt+1)*16;
            const float* bp = bBase + (kt+1)*16;
            ra0 = *(const float4*)(ap);  ra1 = *(const float4*)(ap + 4);
            rb0 = *(const float4*)(bp);  rb1 = *(const float4*)(bp + 4);
        }

        #pragma unroll
        for (int kk = 0; kk < 2; kk++) {
            int kb = kk * 8 + 2*tg;
            unsigned a[4][4];
            #pragma unroll
            for (int mi = 0; mi < 4; mi++) {
                int r = wm*64 + mi*16 + g;
                uint2 lo = *(const uint2*)&As[cur][r][kb];
                uint2 hi = *(const uint2*)&As[cur][r+8][kb];
                a[mi][0] = lo.x; a[mi][1] = hi.x; a[mi][2] = lo.y; a[mi][3] = hi.y;
            }
            unsigned b[4][2];
            #pragma unroll
            for (int ni = 0; ni < 4; ni++) {
                int c = wn*32 + ni*8 + g;
                uint2 bb = *(const uint2*)&Bs[cur][c][kb];
                b[ni][0] = bb.x; b[ni][1] = bb.y;
            }
            #pragma unroll
            for (int mi = 0; mi < 4; mi++)
                #pragma unroll
                for (int ni = 0; ni < 4; ni++)
                    mma8(acc[mi][ni], a[mi][0], a[mi][1], a[mi][2], a[mi][3],
                         b[ni][0], b[ni][1]);
        }

        if (kt < 63) {
            int nxt = cur ^ 1;
            unsigned* ap = &As[nxt][lr][lc];
            ap[0]=f2tf(ra0.x); ap[2]=f2tf(ra0.y); ap[4]=f2tf(ra0.z); ap[6]=f2tf(ra0.w);
            ap[1]=f2tf(ra1.x); ap[3]=f2tf(ra1.y); ap[5]=f2tf(ra1.z); ap[7]=f2tf(ra1.w);
            unsigned* bp = &Bs[nxt][lr][lc];
            bp[0]=f2tf(rb0.x); bp[2]=f2tf(rb0.y); bp[4]=f2tf(rb0.z); bp[6]=f2tf(rb0.w);
            bp[1]=f2tf(rb1.x); bp[3]=f2tf(rb1.y); bp[5]=f2tf(rb1.z); bp[7]=f2tf(rb1.w);
            __syncthreads();
        }
    }

    #pragma unroll
    for (int mi = 0; mi < 4; mi++) {
        #pragma unroll
        for (int hf = 0; hf < 2; hf++) {
            int row = m0 + wm*64 + mi*16 + g + hf*8;
            #pragma unroll
            for (int ni = 0; ni < 4; ni++) {
                int col = n0 + wn*32 + ni*8 + tg*2;
                float2 o = { acc[mi][ni][hf*2+0] + bias[col],
                             acc[mi][ni][hf*2+1] + bias[col+1] };
                *(float2*)&out[(size_t)row * E + col] = o;
            }
        }
    }
}

// ---------------------------------------------------------------------------
extern "C" void kernel_launch(void* const* d_in, const int* in_sizes, int n_in,
                              void* d_out, int out_size)
{
    const float* q   = (const float*)d_in[0];
    const float* k   = (const float*)d_in[1];
    const float* v   = (const float*)d_in[2];
    const float* inw = (const float*)d_in[3];
    const float* inb = (const float*)d_in[4];
    const float* ow  = (const float*)d_in[5];
    const float* ob  = (const float*)d_in[6];

    float* out  = (float*)d_out;
    float* attn = out + OUT0;

    cudaFuncSetAttribute(proj_kernel,    cudaFuncAttributeMaxDynamicSharedMemorySize, PR_SMEM_BYTES);
    cudaFuncSetAttribute(outproj_kernel, cudaFuncAttributeMaxDynamicSharedMemorySize, PR_SMEM_BYTES);
    cudaFuncSetAttribute(scores_kernel,  cudaFuncAttributeMaxDynamicSharedMemorySize, SC_SMEM_BYTES);
    cudaFuncSetAttribute(pv_kernel,      cudaFuncAttributeMaxDynamicSharedMemorySize, PV_SMEM_BYTES);

    proj_kernel<<<dim3(E/128, TB/128, 3), 256, PR_SMEM_BYTES>>>(q, k, v, inw, inb);
    scores_kernel<<<dim3(SQ/128, BH), 256, SC_SMEM_BYTES>>>(attn);
    pv_kernel<<<dim3(SQ/128, BH), 256, PV_SMEM_BYTES>>>(attn);
    outproj_kernel<<<dim3(E/128, TB/128), 256, PR_SMEM_BYTES>>>(ow, ob, out);
}

// round 16
// speedup vs baseline: 1.3134x; 1.0786x over previous
#include <cuda_runtime.h>
#include <math.h>

// Problem constants
#define E   1024
#define NH  16
#define HD  64
#define SQ  2048
#define BS  2
#define TB  (SQ*BS)       // 4096
#define BH  (BS*NH)       // 32
#define OUT0 ((size_t)SQ*BS*E)

// Scratch
__device__ float g_q[BH*SQ*HD];
__device__ float g_k[BH*SQ*HD];
__device__ float g_v[BH*SQ*HD];
__device__ float g_ctx[TB*E];
__device__ float g_rowinv[BH*SQ];

// ---------------------------------------------------------------------------
// helpers
// ---------------------------------------------------------------------------
__device__ __forceinline__ unsigned f2tf(float f) {
    unsigned r;
    asm("cvt.rna.tf32.f32 %0, %1;" : "=r"(r) : "f"(f));
    return r;
}

__device__ __forceinline__ float ex2(float x) {
    float r;
    asm("ex2.approx.f32 %0, %1;" : "=f"(r) : "f"(x));
    return r;
}

__device__ __forceinline__ void mma8(float* c,
                                     unsigned a0, unsigned a1, unsigned a2, unsigned a3,
                                     unsigned b0, unsigned b1) {
    asm volatile(
        "mma.sync.aligned.m16n8k8.row.col.f32.tf32.tf32.f32 "
        "{%0,%1,%2,%3}, {%4,%5,%6,%7}, {%8,%9}, {%0,%1,%2,%3};\n"
        : "+f"(c[0]), "+f"(c[1]), "+f"(c[2]), "+f"(c[3])
        : "r"(a0), "r"(a1), "r"(a2), "r"(a3), "r"(b0), "r"(b1));
}

// ===========================================================================
// Kernel 1: QKV projection (pipelined 128x128 tf32 GEMM, paired LDS). [r14]
// ===========================================================================
#define PR_SMEM_BYTES ((2*128*24 + 2*128*24) * 4)

__global__ void __launch_bounds__(256) proj_kernel(
    const float* __restrict__ qin,
    const float* __restrict__ kin,
    const float* __restrict__ vin,
    const float* __restrict__ w,
    const float* __restrict__ bias)
{
    extern __shared__ __align__(16) unsigned smx[];
    unsigned (*As)[128][24] = reinterpret_cast<unsigned(*)[128][24]>(smx);
    unsigned (*Bs)[128][24] = reinterpret_cast<unsigned(*)[128][24]>(smx + 2*128*24);

    int which = blockIdx.z;
    const float* x  = (which == 0) ? qin : (which == 1) ? kin : vin;
    const float* W  = w + (size_t)which * E * E;
    const float* bv = bias + which * E;
    float* outp = (which == 0) ? g_q : (which == 1) ? g_k : g_v;

    int tid = threadIdx.x;
    int warp = tid >> 5, lane = tid & 31;
    int g = lane >> 2, tg = lane & 3;
    int wm = warp >> 2, wn = warp & 3;
    int m0 = blockIdx.y * 128, n0 = blockIdx.x * 128;

    int lr = tid >> 1;
    int lc = (tid & 1) * 8;

    float4 ra0, ra1, rb0, rb1;
    const float* aBase = x + (size_t)(m0 + lr) * E + lc;
    const float* bBase = W + (size_t)(n0 + lr) * E + lc;

    ra0 = *(const float4*)(aBase);  ra1 = *(const float4*)(aBase + 4);
    rb0 = *(const float4*)(bBase);  rb1 = *(const float4*)(bBase + 4);
    {
        unsigned* ap = &As[0][lr][lc];
        ap[0]=f2tf(ra0.x); ap[2]=f2tf(ra0.y); ap[4]=f2tf(ra0.z); ap[6]=f2tf(ra0.w);
        ap[1]=f2tf(ra1.x); ap[3]=f2tf(ra1.y); ap[5]=f2tf(ra1.z); ap[7]=f2tf(ra1.w);
        unsigned* bp = &Bs[0][lr][lc];
        bp[0]=f2tf(rb0.x); bp[2]=f2tf(rb0.y); bp[4]=f2tf(rb0.z); bp[6]=f2tf(rb0.w);
        bp[1]=f2tf(rb1.x); bp[3]=f2tf(rb1.y); bp[5]=f2tf(rb1.z); bp[7]=f2tf(rb1.w);
    }
    __syncthreads();

    float acc[4][4][4] = {};

    #pragma unroll 1
    for (int kt = 0; kt < 64; kt++) {
        int cur = kt & 1;
        if (kt < 63) {
            const float* ap = aBase + (kt+1)*16;
            const float* bp = bBase + (kt+1)*16;
            ra0 = *(const float4*)(ap);  ra1 = *(const float4*)(ap + 4);
            rb0 = *(const float4*)(bp);  rb1 = *(const float4*)(bp + 4);
        }

        #pragma unroll
        for (int kk = 0; kk < 2; kk++) {
            int kb = kk * 8 + 2*tg;
            unsigned a[4][4];
            #pragma unroll
            for (int mi = 0; mi < 4; mi++) {
                int r = wm*64 + mi*16 + g;
                uint2 lo = *(const uint2*)&As[cur][r][kb];
                uint2 hi = *(const uint2*)&As[cur][r+8][kb];
                a[mi][0] = lo.x; a[mi][1] = hi.x; a[mi][2] = lo.y; a[mi][3] = hi.y;
            }
            unsigned b[4][2];
            #pragma unroll
            for (int ni = 0; ni < 4; ni++) {
                int c = wn*32 + ni*8 + g;
                uint2 bb = *(const uint2*)&Bs[cur][c][kb];
                b[ni][0] = bb.x; b[ni][1] = bb.y;
            }
            #pragma unroll
            for (int mi = 0; mi < 4; mi++)
                #pragma unroll
                for (int ni = 0; ni < 4; ni++)
                    mma8(acc[mi][ni], a[mi][0], a[mi][1], a[mi][2], a[mi][3],
                         b[ni][0], b[ni][1]);
        }

        if (kt < 63) {
            int nxt = cur ^ 1;
            unsigned* ap = &As[nxt][lr][lc];
            ap[0]=f2tf(ra0.x); ap[2]=f2tf(ra0.y); ap[4]=f2tf(ra0.z); ap[6]=f2tf(ra0.w);
            ap[1]=f2tf(ra1.x); ap[3]=f2tf(ra1.y); ap[5]=f2tf(ra1.z); ap[7]=f2tf(ra1.w);
            unsigned* bp = &Bs[nxt][lr][lc];
            bp[0]=f2tf(rb0.x); bp[2]=f2tf(rb0.y); bp[4]=f2tf(rb0.z); bp[6]=f2tf(rb0.w);
            bp[1]=f2tf(rb1.x); bp[3]=f2tf(rb1.y); bp[5]=f2tf(rb1.z); bp[7]=f2tf(rb1.w);
            __syncthreads();
        }
    }

    #pragma unroll
    for (int mi = 0; mi < 4; mi++) {
        #pragma unroll
        for (int hf = 0; hf < 2; hf++) {
            int row = m0 + wm*64 + mi*16 + g + hf*8;
            int t = row >> 1, b = row & 1;
            #pragma unroll
            for (int ni = 0; ni < 4; ni++) {
                int col = n0 + wn*32 + ni*8 + tg*2;
                int h = col >> 6, d = col & 63;
                float2 o = { acc[mi][ni][hf*2+0] + bv[col],
                             acc[mi][ni][hf*2+1] + bv[col+1] };
                *(float2*)&outp[(size_t)(((b<<4) + h) * SQ + t) * HD + d] = o;
            }
        }
    }
}

// ===========================================================================
// Kernel 2: scores -> exp(s) + row sums.  Single K buffer, 2 CTAs/SM.
// Qs interleaved (paired a-frags), scale*log2e folded into Q staging.
// Dyn smem: Qs[128][72] | Ks[128][68] | red_l[128][17]  (~78.5 KB)
// ===========================================================================
#define SC_SMEM_BYTES ((128*72 + 128*68 + 128*17) * 4)

__global__ void __launch_bounds__(256, 2) scores_kernel(float* __restrict__ attn)
{
    extern __shared__ __align__(16) unsigned sm[];
    unsigned (*Qs)[72] = reinterpret_cast<unsigned(*)[72]>(sm);
    unsigned (*Ks)[68] = reinterpret_cast<unsigned(*)[68]>(sm + 128*72);
    float (*red_l)[17] = reinterpret_cast<float(*)[17]>(sm + 128*72 + 128*68);

    int tid = threadIdx.x;
    int warp = tid >> 5, lane = tid & 31;
    int g = lane >> 2, tg = lane & 3;
    int wm = warp >> 2, wn = warp & 3;
    int t0 = blockIdx.x * 128;
    int bh = blockIdx.y;

    const float* qb = g_q + (size_t)bh * SQ * HD;
    const float* kb = g_k + (size_t)bh * SQ * HD;

    int lrow = tid >> 4;          // 0..15
    int lcol = (tid & 15) * 4;    // 0..60
    int pb = (lcol & ~7) + ((lcol >> 2) & 1);   // interleaved base

    const float SCL = 0.125f * 1.44269504089f;  // scale * log2(e)

    // Load Q tile once, scaled, k-interleaved
    #pragma unroll
    for (int j = 0; j < 8; j++) {
        int r = j*16 + lrow;
        float4 a4 = *(const float4*)(qb + (size_t)(t0 + r) * HD + lcol);
        Qs[r][pb+0]=f2tf(a4.x*SCL); Qs[r][pb+2]=f2tf(a4.y*SCL);
        Qs[r][pb+4]=f2tf(a4.z*SCL); Qs[r][pb+6]=f2tf(a4.w*SCL);
    }
    // Load + stage K tile 0 (plain layout)
    float4 kr[8];
    #pragma unroll
    for (int j = 0; j < 8; j++)
        kr[j] = *(const float4*)(kb + (size_t)(j*16 + lrow) * HD + lcol);
    #pragma unroll
    for (int j = 0; j < 8; j++) {
        uint4 t4 = { f2tf(kr[j].x), f2tf(kr[j].y), f2tf(kr[j].z), f2tf(kr[j].w) };
        *(uint4*)&Ks[j*16 + lrow][lcol] = t4;
    }
    __syncthreads();

    float l[4][2];
    #pragma unroll
    for (int mi = 0; mi < 4; mi++) { l[mi][0] = 0.f; l[mi][1] = 0.f; }

    #pragma unroll 1
    for (int st = 0; st < 16; st++) {
        if (st < 15) {
            const float* kp = kb + (size_t)(st+1) * 128 * HD;
            #pragma unroll
            for (int j = 0; j < 8; j++)
                kr[j] = *(const float4*)(kp + (size_t)(j*16 + lrow) * HD + lcol);
        }

        float c[4][4][4];
        #pragma unroll
        for (int mi = 0; mi < 4; mi++)
            #pragma unroll
            for (int ni = 0; ni < 4; ni++)
                #pragma unroll
                for (int q = 0; q < 4; q++) c[mi][ni][q] = 0.f;

        #pragma unroll
        for (int kk = 0; kk < 8; kk++) {
            int kb8 = kk * 8;
            unsigned a[4][4];
            #pragma unroll
            for (int mi = 0; mi < 4; mi++) {
                int r = wm*64 + mi*16 + g;
                uint2 lo = *(const uint2*)&Qs[r][kb8 + 2*tg];
                uint2 hi = *(const uint2*)&Qs[r+8][kb8 + 2*tg];
                a[mi][0] = lo.x; a[mi][1] = hi.x; a[mi][2] = lo.y; a[mi][3] = hi.y;
            }
            unsigned b[4][2];
            #pragma unroll
            for (int ni = 0; ni < 4; ni++) {
                int cx = wn*32 + ni*8 + g;
                b[ni][0] = Ks[cx][kb8+tg];
                b[ni][1] = Ks[cx][kb8+tg+4];
            }
            #pragma unroll
            for (int mi = 0; mi < 4; mi++)
                #pragma unroll
                for (int ni = 0; ni < 4; ni++)
                    mma8(c[mi][ni], a[mi][0], a[mi][1], a[mi][2], a[mi][3],
                         b[ni][0], b[ni][1]);
        }

        // e = 2^c  (c already has scale*log2e); store; accumulate row sums
        #pragma unroll
        for (int mi = 0; mi < 4; mi++) {
            #pragma unroll
            for (int hf = 0; hf < 2; hf++) {
                int tr = t0 + wm*64 + mi*16 + g + hf*8;
                float* pr = attn + ((size_t)bh*SQ + tr)*SQ + st*128 + wn*32 + tg*2;
                float lacc = 0.f;
                #pragma unroll
                for (int ni = 0; ni < 4; ni++) {
                    float e0 = ex2(c[mi][ni][hf*2+0]);
                    float e1 = ex2(c[mi][ni][hf*2+1]);
                    *(float2*)(pr + ni*8) = make_float2(e0, e1);
                    lacc += e0 + e1;
                }
                l[mi][hf] += lacc;
            }
        }

        if (st < 15) {
            __syncthreads();
            #pragma unroll
            for (int j = 0; j < 8; j++) {
                uint4 t4 = { f2tf(kr[j].x), f2tf(kr[j].y), f2tf(kr[j].z), f2tf(kr[j].w) };
                *(uint4*)&Ks[j*16 + lrow][lcol] = t4;
            }
            __syncthreads();
        }
    }

    #pragma unroll
    for (int mi = 0; mi < 4; mi++)
        #pragma unroll
        for (int hf = 0; hf < 2; hf++) {
            int tr = wm*64 + mi*16 + g + hf*8;
            red_l[tr][wn*4 + tg] = l[mi][hf];
        }
    __syncthreads();
    if (tid < 128) {
        float L = 0.f;
        #pragma unroll
        for (int p = 0; p < 16; p++) L += red_l[tid][p];
        g_rowinv[bh*SQ + t0 + tid] = 1.0f / L;
    }
}

// ===========================================================================
// Kernel 3: normalize + write probs + PV MMA.  Single buffers, 2 CTAs/SM.
// Dyn smem: Ps[128][132] | Vs[128][72] | sinv[128]  (~102.5 KB)
// ===========================================================================
#define PV_SMEM_BYTES ((128*132 + 128*72 + 128) * 4)

__global__ void __launch_bounds__(256, 2) pv_kernel(float* __restrict__ attn)
{
    extern __shared__ __align__(16) unsigned sm[];
    unsigned (*Ps)[132] = reinterpret_cast<unsigned(*)[132]>(sm);
    unsigned (*Vs)[72]  = reinterpret_cast<unsigned(*)[72]>(sm + 128*132);
    float* sinv = (float*)(sm + 128*132 + 128*72);

    int tid = threadIdx.x;
    int warp = tid >> 5, lane = tid & 31;
    int g = lane >> 2, tg = lane & 3;
    int wm = warp >> 1, wn = warp & 1;
    int t0 = blockIdx.x * 128;
    int bh = blockIdx.y;
    int b = bh >> 4, h = bh & 15;

    const float* vb = g_v + (size_t)bh * SQ * HD;
    float* pb0 = attn + ((size_t)bh*SQ + t0) * SQ;

    if (tid < 128) sinv[tid] = g_rowinv[bh*SQ + t0 + tid];
    __syncthreads();

    int prow_lo = tid >> 5;
    int pcol = (tid & 31) * 4;
    int vs_lo = tid >> 4;
    int vd0 = (tid & 15) * 4;

    // stage tile 0
    {
        #pragma unroll
        for (int j = 0; j < 16; j += 4) {
            float4 t[4];
            #pragma unroll
            for (int u = 0; u < 4; u++)
                t[u] = *(const float4*)(pb0 + (size_t)((j+u)*8 + prow_lo) * SQ + pcol);
            #pragma unroll
            for (int u = 0; u < 4; u++) {
                int row = (j+u)*8 + prow_lo;
                float inv = sinv[row];
                float4 p = t[u];
                p.x *= inv; p.y *= inv; p.z *= inv; p.w *= inv;
                *(float4*)(pb0 + (size_t)row * SQ + pcol) = p;
                uint4 t4 = { f2tf(p.x), f2tf(p.y), f2tf(p.z), f2tf(p.w) };
                *(uint4*)&Ps[row][pcol] = t4;
            }
        }
        #pragma unroll
        for (int j = 0; j < 8; j += 4) {
            float4 t[4];
            #pragma unroll
            for (int u = 0; u < 4; u++)
                t[u] = *(const float4*)(vb + (size_t)((j+u)*16 + vs_lo) * HD + vd0);
            #pragma unroll
            for (int u = 0; u < 4; u++) {
                uint4 t4 = { f2tf(t[u].x), f2tf(t[u].y), f2tf(t[u].z), f2tf(t[u].w) };
                *(uint4*)&Vs[(j+u)*16 + vs_lo][vd0] = t4;
            }
        }
    }
    __syncthreads();

    float acc[2][4][4] = {};

    #pragma unroll 1
    for (int st = 0; st < 16; st++) {
        #pragma unroll
        for (int kk = 0; kk < 16; kk++) {
            int kb8 = kk * 8;
            unsigned a[2][4];
            #pragma unroll
            for (int mi = 0; mi < 2; mi++) {
                int r = wm*32 + mi*16 + g;
                a[mi][0] = Ps[r][kb8+tg];    a[mi][1] = Ps[r+8][kb8+tg];
                a[mi][2] = Ps[r][kb8+tg+4];  a[mi][3] = Ps[r+8][kb8+tg+4];
            }
            unsigned bb[4][2];
            #pragma unroll
            for (int ni = 0; ni < 4; ni++) {
                int cx = wn*32 + ni*8 + g;
                bb[ni][0] = Vs[kb8+tg][cx];
                bb[ni][1] = Vs[kb8+tg+4][cx];
            }
            #pragma unroll
            for (int mi = 0; mi < 2; mi++)
                #pragma unroll
                for (int ni = 0; ni < 4; ni++)
                    mma8(acc[mi][ni], a[mi][0], a[mi][1], a[mi][2], a[mi][3],
                         bb[ni][0], bb[ni][1]);
        }

        if (st < 15) {
            __syncthreads();
            const float* pp = pb0 + (st+1)*128;
            const float* vp = vb + (size_t)(st+1)*128*HD;
            #pragma unroll
            for (int j = 0; j < 16; j += 4) {
                float4 t[4];
                #pragma unroll
                for (int u = 0; u < 4; u++)
                    t[u] = *(const float4*)(pp + (size_t)((j+u)*8 + prow_lo) * SQ + pcol);
                #pragma unroll
                for (int u = 0; u < 4; u++) {
                    int row = (j+u)*8 + prow_lo;
                    float inv = sinv[row];
                    float4 p = t[u];
                    p.x *= inv; p.y *= inv; p.z *= inv; p.w *= inv;
                    *(float4*)(pb0 + (size_t)row * SQ + (st+1)*128 + pcol) = p;
                    uint4 t4 = { f2tf(p.x), f2tf(p.y), f2tf(p.z), f2tf(p.w) };
                    *(uint4*)&Ps[row][pcol] = t4;
                }
            }
            #pragma unroll
            for (int j = 0; j < 8; j += 4) {
                float4 t[4];
                #pragma unroll
                for (int u = 0; u < 4; u++)
                    t[u] = *(const float4*)(vp + (size_t)((j+u)*16 + vs_lo) * HD + vd0);
                #pragma unroll
                for (int u = 0; u < 4; u++) {
                    uint4 t4 = { f2tf(t[u].x), f2tf(t[u].y), f2tf(t[u].z), f2tf(t[u].w) };
                    *(uint4*)&Vs[(j+u)*16 + vs_lo][vd0] = t4;
                }
            }
            __syncthreads();
        }
    }

    #pragma unroll
    for (int mi = 0; mi < 2; mi++)
        #pragma unroll
        for (int hf = 0; hf < 2; hf++) {
            int t = t0 + wm*32 + mi*16 + g + hf*8;
            #pragma unroll
            for (int ni = 0; ni < 4; ni++) {
                int d = wn*32 + ni*8 + tg*2;
                float2 o = { acc[mi][ni][hf*2+0], acc[mi][ni][hf*2+1] };
                *(float2*)&g_ctx[(size_t)(t*BS + b)*E + h*64 + d] = o;
            }
        }
}

// ===========================================================================
// Kernel 4: out projection (pipelined 128x128 tf32 GEMM, paired LDS). [r14]
// ===========================================================================
__global__ void __launch_bounds__(256) outproj_kernel(
    const float* __restrict__ w,
    const float* __restrict__ bias,
    float* __restrict__ out)
{
    extern __shared__ __align__(16) unsigned smx[];
    unsigned (*As)[128][24] = reinterpret_cast<unsigned(*)[128][24]>(smx);
    unsigned (*Bs)[128][24] = reinterpret_cast<unsigned(*)[128][24]>(smx + 2*128*24);

    int tid = threadIdx.x;
    int warp = tid >> 5, lane = tid & 31;
    int g = lane >> 2, tg = lane & 3;
    int wm = warp >> 2, wn = warp & 3;
    int m0 = blockIdx.y * 128, n0 = blockIdx.x * 128;

    int lr = tid >> 1;
    int lc = (tid & 1) * 8;

    float4 ra0, ra1, rb0, rb1;
    const float* aBase = g_ctx + (size_t)(m0 + lr) * E + lc;
    const float* bBase = w + (size_t)(n0 + lr) * E + lc;

    ra0 = *(const float4*)(aBase);  ra1 = *(const float4*)(aBase + 4);
    rb0 = *(const float4*)(bBase);  rb1 = *(const float4*)(bBase + 4);
    {
        unsigned* ap = &As[0][lr][lc];
        ap[0]=f2tf(ra0.x); ap[2]=f2tf(ra0.y); ap[4]=f2tf(ra0.z); ap[6]=f2tf(ra0.w);
        ap[1]=f2tf(ra1.x); ap[3]=f2tf(ra1.y); ap[5]=f2tf(ra1.z); ap[7]=f2tf(ra1.w);
        unsigned* bp = &Bs[0][lr][lc];
        bp[0]=f2tf(rb0.x); bp[2]=f2tf(rb0.y); bp[4]=f2tf(rb0.z); bp[6]=f2tf(rb0.w);
        bp[1]=f2tf(rb1.x); bp[3]=f2tf(rb1.y); bp[5]=f2tf(rb1.z); bp[7]=f2tf(rb1.w);
    }
    __syncthreads();

    float acc[4][4][4] = {};

    #pragma unroll 1
    for (int kt = 0; kt < 64; kt++) {
        int cur = kt & 1;
        if (kt < 63) {
            const float* ap = aBase + (kt+1)*16;
            const float* bp = bBase + (kt+1)*16;
            ra0 = *(const float4*)(ap);  ra1 = *(const float4*)(ap + 4);
            rb0 = *(const float4*)(bp);  rb1 = *(const float4*)(bp + 4);
        }

        #pragma unroll
        for (int kk = 0; kk < 2; kk++) {
            int kb = kk * 8 + 2*tg;
            unsigned a[4][4];
            #pragma unroll
            for (int mi = 0; mi < 4; mi++) {
                int r = wm*64 + mi*16 + g;
                uint2 lo = *(const uint2*)&As[cur][r][kb];
                uint2 hi = *(const uint2*)&As[cur][r+8][kb];
                a[mi][0] = lo.x; a[mi][1] = hi.x; a[mi][2] = lo.y; a[mi][3] = hi.y;
            }
            unsigned b[4][2];
            #pragma unroll
            for (int ni = 0; ni < 4; ni++) {
                int c = wn*32 + ni*8 + g;
                uint2 bb = *(const uint2*)&Bs[cur][c][kb];
                b[ni][0] = bb.x; b[ni][1] = bb.y;
            }
            #pragma unroll
            for (int mi = 0; mi < 4; mi++)
                #pragma unroll
                for (int ni = 0; ni < 4; ni++)
                    mma8(acc[mi][ni], a[mi][0], a[mi][1], a[mi][2], a[mi][3],
                         b[ni][0], b[ni][1]);
        }

        if (kt < 63) {
            int nxt = cur ^ 1;
            unsigned* ap = &As[nxt][lr][lc];
            ap[0]=f2tf(ra0.x); ap[2]=f2tf(ra0.y); ap[4]=f2tf(ra0.z); ap[6]=f2tf(ra0.w);
            ap[1]=f2tf(ra1.x); ap[3]=f2tf(ra1.y); ap[5]=f2tf(ra1.z); ap[7]=f2tf(ra1.w);
            unsigned* bp = &Bs[nxt][lr][lc];
            bp[0]=f2tf(rb0.x); bp[2]=f2tf(rb0.y); bp[4]=f2tf(rb0.z); bp[6]=f2tf(rb0.w);
            bp[1]=f2tf(rb1.x); bp[3]=f2tf(rb1.y); bp[5]=f2tf(rb1.z); bp[7]=f2tf(rb1.w);
            __syncthreads();
        }
    }

    #pragma unroll
    for (int mi = 0; mi < 4; mi++) {
        #pragma unroll
        for (int hf = 0; hf < 2; hf++) {
            int row = m0 + wm*64 + mi*16 + g + hf*8;
            #pragma unroll
            for (int ni = 0; ni < 4; ni++) {
                int col = n0 + wn*32 + ni*8 + tg*2;
                float2 o = { acc[mi][ni][hf*2+0] + bias[col],
                             acc[mi][ni][hf*2+1] + bias[col+1] };
                *(float2*)&out[(size_t)row * E + col] = o;
            }
        }
    }
}

// ---------------------------------------------------------------------------
extern "C" void kernel_launch(void* const* d_in, const int* in_sizes, int n_in,
                              void* d_out, int out_size)
{
    const float* q   = (const float*)d_in[0];
    const float* k   = (const float*)d_in[1];
    const float* v   = (const float*)d_in[2];
    const float* inw = (const float*)d_in[3];
    const float* inb = (const float*)d_in[4];
    const float* ow  = (const float*)d_in[5];
    const float* ob  = (const float*)d_in[6];

    float* out  = (float*)d_out;
    float* attn = out + OUT0;

    cudaFuncSetAttribute(proj_kernel,    cudaFuncAttributeMaxDynamicSharedMemorySize, PR_SMEM_BYTES);
    cudaFuncSetAttribute(outproj_kernel, cudaFuncAttributeMaxDynamicSharedMemorySize, PR_SMEM_BYTES);
    cudaFuncSetAttribute(scores_kernel,  cudaFuncAttributeMaxDynamicSharedMemorySize, SC_SMEM_BYTES);
    cudaFuncSetAttribute(pv_kernel,      cudaFuncAttributeMaxDynamicSharedMemorySize, PV_SMEM_BYTES);

    proj_kernel<<<dim3(E/128, TB/128, 3), 256, PR_SMEM_BYTES>>>(q, k, v, inw, inb);
    scores_kernel<<<dim3(SQ/128, BH), 256, SC_SMEM_BYTES>>>(attn);
    pv_kernel<<<dim3(SQ/128, BH), 256, PV_SMEM_BYTES>>>(attn);
    outproj_kernel<<<dim3(E/128, TB/128), 256, PR_SMEM_BYTES>>>(ow, ob, out);
}

// round 17
// speedup vs baseline: 1.3489x; 1.0270x over previous
#include <cuda_runtime.h>
#include <cuda_fp16.h>
#include <math.h>

// Problem constants
#define E   1024
#define NH  16
#define HD  64
#define SQ  2048
#define BS  2
#define TB  (SQ*BS)       // 4096
#define BH  (BS*NH)       // 32
#define OUT0 ((size_t)SQ*BS*E)

// Scratch
__device__ float g_q[BH*SQ*HD];
__device__ float g_k[BH*SQ*HD];
__device__ float g_v[BH*SQ*HD];
__device__ float g_ctx[TB*E];
__device__ float g_rowinv[BH*SQ];
__device__ __half g_e[134217728];   // BH*SQ*SQ raw exp scores, fp16 (268MB)

// ---------------------------------------------------------------------------
// helpers
// ---------------------------------------------------------------------------
__device__ __forceinline__ unsigned f2tf(float f) {
    unsigned r;
    asm("cvt.rna.tf32.f32 %0, %1;" : "=r"(r) : "f"(f));
    return r;
}

__device__ __forceinline__ float ex2(float x) {
    float r;
    asm("ex2.approx.f32 %0, %1;" : "=f"(r) : "f"(x));
    return r;
}

__device__ __forceinline__ void mma8(float* c,
                                     unsigned a0, unsigned a1, unsigned a2, unsigned a3,
                                     unsigned b0, unsigned b1) {
    asm volatile(
        "mma.sync.aligned.m16n8k8.row.col.f32.tf32.tf32.f32 "
        "{%0,%1,%2,%3}, {%4,%5,%6,%7}, {%8,%9}, {%0,%1,%2,%3};\n"
        : "+f"(c[0]), "+f"(c[1]), "+f"(c[2]), "+f"(c[3])
        : "r"(a0), "r"(a1), "r"(a2), "r"(a3), "r"(b0), "r"(b1));
}

// ===========================================================================
// Kernel 1: QKV projection (pipelined 128x128 tf32 GEMM, paired LDS). [r16]
// ===========================================================================
#define PR_SMEM_BYTES ((2*128*24 + 2*128*24) * 4)

__global__ void __launch_bounds__(256) proj_kernel(
    const float* __restrict__ qin,
    const float* __restrict__ kin,
    const float* __restrict__ vin,
    const float* __restrict__ w,
    const float* __restrict__ bias)
{
    extern __shared__ __align__(16) unsigned smx[];
    unsigned (*As)[128][24] = reinterpret_cast<unsigned(*)[128][24]>(smx);
    unsigned (*Bs)[128][24] = reinterpret_cast<unsigned(*)[128][24]>(smx + 2*128*24);

    int which = blockIdx.z;
    const float* x  = (which == 0) ? qin : (which == 1) ? kin : vin;
    const float* W  = w + (size_t)which * E * E;
    const float* bv = bias + which * E;
    float* outp = (which == 0) ? g_q : (which == 1) ? g_k : g_v;

    int tid = threadIdx.x;
    int warp = tid >> 5, lane = tid & 31;
    int g = lane >> 2, tg = lane & 3;
    int wm = warp >> 2, wn = warp & 3;
    int m0 = blockIdx.y * 128, n0 = blockIdx.x * 128;

    int lr = tid >> 1;
    int lc = (tid & 1) * 8;

    float4 ra0, ra1, rb0, rb1;
    const float* aBase = x + (size_t)(m0 + lr) * E + lc;
    const float* bBase = W + (size_t)(n0 + lr) * E + lc;

    ra0 = *(const float4*)(aBase);  ra1 = *(const float4*)(aBase + 4);
    rb0 = *(const float4*)(bBase);  rb1 = *(const float4*)(bBase + 4);
    {
        unsigned* ap = &As[0][lr][lc];
        ap[0]=f2tf(ra0.x); ap[2]=f2tf(ra0.y); ap[4]=f2tf(ra0.z); ap[6]=f2tf(ra0.w);
        ap[1]=f2tf(ra1.x); ap[3]=f2tf(ra1.y); ap[5]=f2tf(ra1.z); ap[7]=f2tf(ra1.w);
        unsigned* bp = &Bs[0][lr][lc];
        bp[0]=f2tf(rb0.x); bp[2]=f2tf(rb0.y); bp[4]=f2tf(rb0.z); bp[6]=f2tf(rb0.w);
        bp[1]=f2tf(rb1.x); bp[3]=f2tf(rb1.y); bp[5]=f2tf(rb1.z); bp[7]=f2tf(rb1.w);
    }
    __syncthreads();

    float acc[4][4][4] = {};

    #pragma unroll 1
    for (int kt = 0; kt < 64; kt++) {
        int cur = kt & 1;
        if (kt < 63) {
            const float* ap = aBase + (kt+1)*16;
            const float* bp = bBase + (kt+1)*16;
            ra0 = *(const float4*)(ap);  ra1 = *(const float4*)(ap + 4);
            rb0 = *(const float4*)(bp);  rb1 = *(const float4*)(bp + 4);
        }

        #pragma unroll
        for (int kk = 0; kk < 2; kk++) {
            int kb = kk * 8 + 2*tg;
            unsigned a[4][4];
            #pragma unroll
            for (int mi = 0; mi < 4; mi++) {
                int r = wm*64 + mi*16 + g;
                uint2 lo = *(const uint2*)&As[cur][r][kb];
                uint2 hi = *(const uint2*)&As[cur][r+8][kb];
                a[mi][0] = lo.x; a[mi][1] = hi.x; a[mi][2] = lo.y; a[mi][3] = hi.y;
            }
            unsigned b[4][2];
            #pragma unroll
            for (int ni = 0; ni < 4; ni++) {
                int c = wn*32 + ni*8 + g;
                uint2 bb = *(const uint2*)&Bs[cur][c][kb];
                b[ni][0] = bb.x; b[ni][1] = bb.y;
            }
            #pragma unroll
            for (int mi = 0; mi < 4; mi++)
                #pragma unroll
                for (int ni = 0; ni < 4; ni++)
                    mma8(acc[mi][ni], a[mi][0], a[mi][1], a[mi][2], a[mi][3],
                         b[ni][0], b[ni][1]);
        }

        if (kt < 63) {
            int nxt = cur ^ 1;
            unsigned* ap = &As[nxt][lr][lc];
            ap[0]=f2tf(ra0.x); ap[2]=f2tf(ra0.y); ap[4]=f2tf(ra0.z); ap[6]=f2tf(ra0.w);
            ap[1]=f2tf(ra1.x); ap[3]=f2tf(ra1.y); ap[5]=f2tf(ra1.z); ap[7]=f2tf(ra1.w);
            unsigned* bp = &Bs[nxt][lr][lc];
            bp[0]=f2tf(rb0.x); bp[2]=f2tf(rb0.y); bp[4]=f2tf(rb0.z); bp[6]=f2tf(rb0.w);
            bp[1]=f2tf(rb1.x); bp[3]=f2tf(rb1.y); bp[5]=f2tf(rb1.z); bp[7]=f2tf(rb1.w);
            __syncthreads();
        }
    }

    #pragma unroll
    for (int mi = 0; mi < 4; mi++) {
        #pragma unroll
        for (int hf = 0; hf < 2; hf++) {
            int row = m0 + wm*64 + mi*16 + g + hf*8;
            int t = row >> 1, b = row & 1;
            #pragma unroll
            for (int ni = 0; ni < 4; ni++) {
                int col = n0 + wn*32 + ni*8 + tg*2;
                int h = col >> 6, d = col & 63;
                float2 o = { acc[mi][ni][hf*2+0] + bv[col],
                             acc[mi][ni][hf*2+1] + bv[col+1] };
                *(float2*)&outp[(size_t)(((b<<4) + h) * SQ + t) * HD + d] = o;
            }
        }
    }
}

// ===========================================================================
// Kernel 2: scores -> exp(s) (fp16) + row sums.  Single K buffer, 2 CTAs/SM.
// Dyn smem: Qs[128][72] | Ks[128][68] | red_l[128][17]  (~78.5 KB)
// ===========================================================================
#define SC_SMEM_BYTES ((128*72 + 128*68 + 128*17) * 4)

__global__ void __launch_bounds__(256, 2) scores_kernel()
{
    extern __shared__ __align__(16) unsigned sm[];
    unsigned (*Qs)[72] = reinterpret_cast<unsigned(*)[72]>(sm);
    unsigned (*Ks)[68] = reinterpret_cast<unsigned(*)[68]>(sm + 128*72);
    float (*red_l)[17] = reinterpret_cast<float(*)[17]>(sm + 128*72 + 128*68);

    int tid = threadIdx.x;
    int warp = tid >> 5, lane = tid & 31;
    int g = lane >> 2, tg = lane & 3;
    int wm = warp >> 2, wn = warp & 3;
    int t0 = blockIdx.x * 128;
    int bh = blockIdx.y;

    const float* qb = g_q + (size_t)bh * SQ * HD;
    const float* kb = g_k + (size_t)bh * SQ * HD;

    int lrow = tid >> 4;          // 0..15
    int lcol = (tid & 15) * 4;    // 0..60
    int pb = (lcol & ~7) + ((lcol >> 2) & 1);   // interleaved base

    const float SCL = 0.125f * 1.44269504089f;  // scale * log2(e)

    // Load Q tile once, scaled, k-interleaved
    #pragma unroll
    for (int j = 0; j < 8; j++) {
        int r = j*16 + lrow;
        float4 a4 = *(const float4*)(qb + (size_t)(t0 + r) * HD + lcol);
        Qs[r][pb+0]=f2tf(a4.x*SCL); Qs[r][pb+2]=f2tf(a4.y*SCL);
        Qs[r][pb+4]=f2tf(a4.z*SCL); Qs[r][pb+6]=f2tf(a4.w*SCL);
    }
    // Load + stage K tile 0
    float4 kr[8];
    #pragma unroll
    for (int j = 0; j < 8; j++)
        kr[j] = *(const float4*)(kb + (size_t)(j*16 + lrow) * HD + lcol);
    #pragma unroll
    for (int j = 0; j < 8; j++) {
        uint4 t4 = { f2tf(kr[j].x), f2tf(kr[j].y), f2tf(kr[j].z), f2tf(kr[j].w) };
        *(uint4*)&Ks[j*16 + lrow][lcol] = t4;
    }
    __syncthreads();

    float l[4][2];
    #pragma unroll
    for (int mi = 0; mi < 4; mi++) { l[mi][0] = 0.f; l[mi][1] = 0.f; }

    #pragma unroll 1
    for (int st = 0; st < 16; st++) {
        if (st < 15) {
            const float* kp = kb + (size_t)(st+1) * 128 * HD;
            #pragma unroll
            for (int j = 0; j < 8; j++)
                kr[j] = *(const float4*)(kp + (size_t)(j*16 + lrow) * HD + lcol);
        }

        float c[4][4][4];
        #pragma unroll
        for (int mi = 0; mi < 4; mi++)
            #pragma unroll
            for (int ni = 0; ni < 4; ni++)
                #pragma unroll
                for (int q = 0; q < 4; q++) c[mi][ni][q] = 0.f;

        #pragma unroll
        for (int kk = 0; kk < 8; kk++) {
            int kb8 = kk * 8;
            unsigned a[4][4];
            #pragma unroll
            for (int mi = 0; mi < 4; mi++) {
                int r = wm*64 + mi*16 + g;
                uint2 lo = *(const uint2*)&Qs[r][kb8 + 2*tg];
                uint2 hi = *(const uint2*)&Qs[r+8][kb8 + 2*tg];
                a[mi][0] = lo.x; a[mi][1] = hi.x; a[mi][2] = lo.y; a[mi][3] = hi.y;
            }
            unsigned b[4][2];
            #pragma unroll
            for (int ni = 0; ni < 4; ni++) {
                int cx = wn*32 + ni*8 + g;
                b[ni][0] = Ks[cx][kb8+tg];
                b[ni][1] = Ks[cx][kb8+tg+4];
            }
            #pragma unroll
            for (int mi = 0; mi < 4; mi++)
                #pragma unroll
                for (int ni = 0; ni < 4; ni++)
                    mma8(c[mi][ni], a[mi][0], a[mi][1], a[mi][2], a[mi][3],
                         b[ni][0], b[ni][1]);
        }

        // e = 2^c; store fp16; accumulate row sums (f32, pre-quantization)
        #pragma unroll
        for (int mi = 0; mi < 4; mi++) {
            #pragma unroll
            for (int hf = 0; hf < 2; hf++) {
                int tr = t0 + wm*64 + mi*16 + g + hf*8;
                __half* pe = g_e + ((size_t)bh*SQ + tr)*SQ + st*128 + wn*32 + tg*2;
                float lacc = 0.f;
                #pragma unroll
                for (int ni = 0; ni < 4; ni++) {
                    float e0 = ex2(c[mi][ni][hf*2+0]);
                    float e1 = ex2(c[mi][ni][hf*2+1]);
                    *(__half2*)(pe + ni*8) = __floats2half2_rn(e0, e1);
                    lacc += e0 + e1;
                }
                l[mi][hf] += lacc;
            }
        }

        if (st < 15) {
            __syncthreads();
            #pragma unroll
            for (int j = 0; j < 8; j++) {
                uint4 t4 = { f2tf(kr[j].x), f2tf(kr[j].y), f2tf(kr[j].z), f2tf(kr[j].w) };
                *(uint4*)&Ks[j*16 + lrow][lcol] = t4;
            }
            __syncthreads();
        }
    }

    #pragma unroll
    for (int mi = 0; mi < 4; mi++)
        #pragma unroll
        for (int hf = 0; hf < 2; hf++) {
            int tr = wm*64 + mi*16 + g + hf*8;
            red_l[tr][wn*4 + tg] = l[mi][hf];
        }
    __syncthreads();
    if (tid < 128) {
        float L = 0.f;
        #pragma unroll
        for (int p = 0; p < 16; p++) L += red_l[tid][p];
        g_rowinv[bh*SQ + t0 + tid] = 1.0f / L;
    }
}

// ===========================================================================
// Kernel 3: read fp16 e, normalize -> write f32 probs + PV MMA.  2 CTAs/SM.
// Dyn smem: Ps[128][132] | Vs[128][72] | sinv[128]  (~102.5 KB)
// ===========================================================================
#define PV_SMEM_BYTES ((128*132 + 128*72 + 128) * 4)

__global__ void __launch_bounds__(256, 2) pv_kernel(float* __restrict__ attn)
{
    extern __shared__ __align__(16) unsigned sm[];
    unsigned (*Ps)[132] = reinterpret_cast<unsigned(*)[132]>(sm);
    unsigned (*Vs)[72]  = reinterpret_cast<unsigned(*)[72]>(sm + 128*132);
    float* sinv = (float*)(sm + 128*132 + 128*72);

    int tid = threadIdx.x;
    int warp = tid >> 5, lane = tid & 31;
    int g = lane >> 2, tg = lane & 3;
    int wm = warp >> 1, wn = warp & 1;
    int t0 = blockIdx.x * 128;
    int bh = blockIdx.y;
    int b = bh >> 4, h = bh & 15;

    const float* vb = g_v + (size_t)bh * SQ * HD;
    const __half* pe0 = g_e + ((size_t)bh*SQ + t0) * SQ;
    float* po0 = attn + ((size_t)bh*SQ + t0) * SQ;

    if (tid < 128) sinv[tid] = g_rowinv[bh*SQ + t0 + tid];
    __syncthreads();

    int prow_lo = tid >> 5;
    int pcol = (tid & 31) * 4;
    int vs_lo = tid >> 4;
    int vd0 = (tid & 15) * 4;

    // stage tile 0
    {
        #pragma unroll
        for (int j = 0; j < 16; j += 4) {
            uint2 t[4];
            #pragma unroll
            for (int u = 0; u < 4; u++)
                t[u] = *(const uint2*)(pe0 + (size_t)((j+u)*8 + prow_lo) * SQ + pcol);
            #pragma unroll
            for (int u = 0; u < 4; u++) {
                int row = (j+u)*8 + prow_lo;
                float inv = sinv[row];
                float2 lo = __half22float2(((const __half2*)&t[u])[0]);
                float2 hi = __half22float2(((const __half2*)&t[u])[1]);
                float4 p = { lo.x*inv, lo.y*inv, hi.x*inv, hi.y*inv };
                *(float4*)(po0 + (size_t)row * SQ + pcol) = p;
                uint4 t4 = { f2tf(p.x), f2tf(p.y), f2tf(p.z), f2tf(p.w) };
                *(uint4*)&Ps[row][pcol] = t4;
            }
        }
        #pragma unroll
        for (int j = 0; j < 8; j += 4) {
            float4 t[4];
            #pragma unroll
            for (int u = 0; u < 4; u++)
                t[u] = *(const float4*)(vb + (size_t)((j+u)*16 + vs_lo) * HD + vd0);
            #pragma unroll
            for (int u = 0; u < 4; u++) {
                uint4 t4 = { f2tf(t[u].x), f2tf(t[u].y), f2tf(t[u].z), f2tf(t[u].w) };
                *(uint4*)&Vs[(j+u)*16 + vs_lo][vd0] = t4;
            }
        }
    }
    __syncthreads();

    float acc[2][4][4] = {};

    #pragma unroll 1
    for (int st = 0; st < 16; st++) {
        #pragma unroll
        for (int kk = 0; kk < 16; kk++) {
            int kb8 = kk * 8;
            unsigned a[2][4];
            #pragma unroll
            for (int mi = 0; mi < 2; mi++) {
                int r = wm*32 + mi*16 + g;
                a[mi][0] = Ps[r][kb8+tg];    a[mi][1] = Ps[r+8][kb8+tg];
                a[mi][2] = Ps[r][kb8+tg+4];  a[mi][3] = Ps[r+8][kb8+tg+4];
            }
            unsigned bb[4][2];
            #pragma unroll
            for (int ni = 0; ni < 4; ni++) {
                int cx = wn*32 + ni*8 + g;
                bb[ni][0] = Vs[kb8+tg][cx];
                bb[ni][1] = Vs[kb8+tg+4][cx];
            }
            #pragma unroll
            for (int mi = 0; mi < 2; mi++)
                #pragma unroll
                for (int ni = 0; ni < 4; ni++)
                    mma8(acc[mi][ni], a[mi][0], a[mi][1], a[mi][2], a[mi][3],
                         bb[ni][0], bb[ni][1]);
        }

        if (st < 15) {
            __syncthreads();
            const __half* pp = pe0 + (st+1)*128;
            float* pw = po0 + (st+1)*128;
            const float* vp = vb + (size_t)(st+1)*128*HD;
            #pragma unroll
            for (int j = 0; j < 16; j += 4) {
                uint2 t[4];
                #pragma unroll
                for (int u = 0; u < 4; u++)
                    t[u] = *(const uint2*)(pp + (size_t)((j+u)*8 + prow_lo) * SQ + pcol);
                #pragma unroll
                for (int u = 0; u < 4; u++) {
                    int row = (j+u)*8 + prow_lo;
                    float inv = sinv[row];
                    float2 lo = __half22float2(((const __half2*)&t[u])[0]);
                    float2 hi = __half22float2(((const __half2*)&t[u])[1]);
                    float4 p = { lo.x*inv, lo.y*inv, hi.x*inv, hi.y*inv };
                    *(float4*)(pw + (size_t)row * SQ + pcol) = p;
                    uint4 t4 = { f2tf(p.x), f2tf(p.y), f2tf(p.z), f2tf(p.w) };
                    *(uint4*)&Ps[row][pcol] = t4;
                }
            }
            #pragma unroll
            for (int j = 0; j < 8; j += 4) {
                float4 t[4];
                #pragma unroll
                for (int u = 0; u < 4; u++)
                    t[u] = *(const float4*)(vp + (size_t)((j+u)*16 + vs_lo) * HD + vd0);
                #pragma unroll
                for (int u = 0; u < 4; u++) {
                    uint4 t4 = { f2tf(t[u].x), f2tf(t[u].y), f2tf(t[u].z), f2tf(t[u].w) };
                    *(uint4*)&Vs[(j+u)*16 + vs_lo][vd0] = t4;
                }
            }
            __syncthreads();
        }
    }

    #pragma unroll
    for (int mi = 0; mi < 2; mi++)
        #pragma unroll
        for (int hf = 0; hf < 2; hf++) {
            int t = t0 + wm*32 + mi*16 + g + hf*8;
            #pragma unroll
            for (int ni = 0; ni < 4; ni++) {
                int d = wn*32 + ni*8 + tg*2;
                float2 o = { acc[mi][ni][hf*2+0], acc[mi][ni][hf*2+1] };
                *(float2*)&g_ctx[(size_t)(t*BS + b)*E + h*64 + d] = o;
            }
        }
}

// ===========================================================================
// Kernel 4: out projection (pipelined 128x128 tf32 GEMM, paired LDS). [r16]
// ===========================================================================
__global__ void __launch_bounds__(256) outproj_kernel(
    const float* __restrict__ w,
    const float* __restrict__ bias,
    float* __restrict__ out)
{
    extern __shared__ __align__(16) unsigned smx[];
    unsigned (*As)[128][24] = reinterpret_cast<unsigned(*)[128][24]>(smx);
    unsigned (*Bs)[128][24] = reinterpret_cast<unsigned(*)[128][24]>(smx + 2*128*24);

    int tid = threadIdx.x;
    int warp = tid >> 5, lane = tid & 31;
    int g = lane >> 2, tg = lane & 3;
    int wm = warp >> 2, wn = warp & 3;
    int m0 = blockIdx.y * 128, n0 = blockIdx.x * 128;

    int lr = tid >> 1;
    int lc = (tid & 1) * 8;

    float4 ra0, ra1, rb0, rb1;
    const float* aBase = g_ctx + (size_t)(m0 + lr) * E + lc;
    const float* bBase = w + (size_t)(n0 + lr) * E + lc;

    ra0 = *(const float4*)(aBase);  ra1 = *(const float4*)(aBase + 4);
    rb0 = *(const float4*)(bBase);  rb1 = *(const float4*)(bBase + 4);
    {
        unsigned* ap = &As[0][lr][lc];
        ap[0]=f2tf(ra0.x); ap[2]=f2tf(ra0.y); ap[4]=f2tf(ra0.z); ap[6]=f2tf(ra0.w);
        ap[1]=f2tf(ra1.x); ap[3]=f2tf(ra1.y); ap[5]=f2tf(ra1.z); ap[7]=f2tf(ra1.w);
        unsigned* bp = &Bs[0][lr][lc];
        bp[0]=f2tf(rb0.x); bp[2]=f2tf(rb0.y); bp[4]=f2tf(rb0.z); bp[6]=f2tf(rb0.w);
        bp[1]=f2tf(rb1.x); bp[3]=f2tf(rb1.y); bp[5]=f2tf(rb1.z); bp[7]=f2tf(rb1.w);
    }
    __syncthreads();

    float acc[4][4][4] = {};

    #pragma unroll 1
    for (int kt = 0; kt < 64; kt++) {
        int cur = kt & 1;
        if (kt < 63) {
            const float* ap = aBase + (kt+1)*16;
            const float* bp = bBase + (kt+1)*16;
            ra0 = *(const float4*)(ap);  ra1 = *(const float4*)(ap + 4);
            rb0 = *(const float4*)(bp);  rb1 = *(const float4*)(bp + 4);
        }

        #pragma unroll
        for (int kk = 0; kk < 2; kk++) {
            int kb = kk * 8 + 2*tg;
            unsigned a[4][4];
            #pragma unroll
            for (int mi = 0; mi < 4; mi++) {
                int r = wm*64 + mi*16 + g;
                uint2 lo = *(const uint2*)&As[cur][r][kb];
                uint2 hi = *(const uint2*)&As[cur][r+8][kb];
                a[mi][0] = lo.x; a[mi][1] = hi.x; a[mi][2] = lo.y; a[mi][3] = hi.y;
            }
            unsigned b[4][2];
            #pragma unroll
            for (int ni = 0; ni < 4; ni++) {
                int c = wn*32 + ni*8 + g;
                uint2 bb = *(const uint2*)&Bs[cur][c][kb];
                b[ni][0] = bb.x; b[ni][1] = bb.y;
            }
            #pragma unroll
            for (int mi = 0; mi < 4; mi++)
                #pragma unroll
                for (int ni = 0; ni < 4; ni++)
                    mma8(acc[mi][ni], a[mi][0], a[mi][1], a[mi][2], a[mi][3],
                         b[ni][0], b[ni][1]);
        }

        if (kt < 63) {
            int nxt = cur ^ 1;
            unsigned* ap = &As[nxt][lr][lc];
            ap[0]=f2tf(ra0.x); ap[2]=f2tf(ra0.y); ap[4]=f2tf(ra0.z); ap[6]=f2tf(ra0.w);
            ap[1]=f2tf(ra1.x); ap[3]=f2tf(ra1.y); ap[5]=f2tf(ra1.z); ap[7]=f2tf(ra1.w);
            unsigned* bp = &Bs[nxt][lr][lc];
            bp[0]=f2tf(rb0.x); bp[2]=f2tf(rb0.y); bp[4]=f2tf(rb0.z); bp[6]=f2tf(rb0.w);
            bp[1]=f2tf(rb1.x); bp[3]=f2tf(rb1.y); bp[5]=f2tf(rb1.z); bp[7]=f2tf(rb1.w);
            __syncthreads();
        }
    }

    #pragma unroll
    for (int mi = 0; mi < 4; mi++) {
        #pragma unroll
        for (int hf = 0; hf < 2; hf++) {
            int row = m0 + wm*64 + mi*16 + g + hf*8;
            #pragma unroll
            for (int ni = 0; ni < 4; ni++) {
                int col = n0 + wn*32 + ni*8 + tg*2;
                float2 o = { acc[mi][ni][hf*2+0] + bias[col],
                             acc[mi][ni][hf*2+1] + bias[col+1] };
                *(float2*)&out[(size_t)row * E + col] = o;
            }
        }
    }
}

// ---------------------------------------------------------------------------
extern "C" void kernel_launch(void* const* d_in, const int* in_sizes, int n_in,
                              void* d_out, int out_size)
{
    const float* q   = (const float*)d_in[0];
    const float* k   = (const float*)d_in[1];
    const float* v   = (const float*)d_in[2];
    const float* inw = (const float*)d_in[3];
    const float* inb = (const float*)d_in[4];
    const float* ow  = (const float*)d_in[5];
    const float* ob  = (const float*)d_in[6];

    float* out  = (float*)d_out;
    float* attn = out + OUT0;

    cudaFuncSetAttribute(proj_kernel,    cudaFuncAttributeMaxDynamicSharedMemorySize, PR_SMEM_BYTES);
    cudaFuncSetAttribute(outproj_kernel, cudaFuncAttributeMaxDynamicSharedMemorySize, PR_SMEM_BYTES);
    cudaFuncSetAttribute(scores_kernel,  cudaFuncAttributeMaxDynamicSharedMemorySize, SC_SMEM_BYTES);
    cudaFuncSetAttribute(pv_kernel,      cudaFuncAttributeMaxDynamicSharedMemorySize, PV_SMEM_BYTES);

    proj_kernel<<<dim3(E/128, TB/128, 3), 256, PR_SMEM_BYTES>>>(q, k, v, inw, inb);
    scores_kernel<<<dim3(SQ/128, BH), 256, SC_SMEM_BYTES>>>();
    pv_kernel<<<dim3(SQ/128, BH), 256, PV_SMEM_BYTES>>>(attn);
    outproj_kernel<<<dim3(E/128, TB/128), 256, PR_SMEM_BYTES>>>(ow, ob, out);
}